// round 1
// baseline (speedup 1.0000x reference)
#include <cuda_runtime.h>
#include <cuda_bf16.h>
#include <math.h>

#define B_   2
#define T_   2048
#define DIM_ 1024
#define NH_  16
#define HD_  64

// Scratch (alloc-free rule: __device__ globals)
__device__ float g_qkv[(size_t)B_ * T_ * 3 * DIM_];   // [B,T, 3*DIM] : q|k|v
__device__ float g_y  [(size_t)B_ * T_ * DIM_];       // attention output [B,T,DIM]

// ---------------------------------------------------------------------------
// Tiled SGEMM: C[M,N] = A[M,K] @ B[K,N], row-major, 64x64 tile, BK=16,
// 256 threads, 4x4 register tile per thread.
// ---------------------------------------------------------------------------
__global__ __launch_bounds__(256) void sgemm64(const float* __restrict__ A,
                                               const float* __restrict__ Bm,
                                               float* __restrict__ C,
                                               int M, int N, int K) {
    __shared__ float As[16][65];   // [k][m], padded
    __shared__ float Bs[16][64];   // [k][n], float4-aligned rows

    const int tid = threadIdx.x;
    const int ty = tid >> 4;        // 0..15
    const int tx = tid & 15;        // 0..15
    const int m0 = blockIdx.y * 64;
    const int n0 = blockIdx.x * 64;

    // load indices
    const int lm = tid >> 2;             // 0..63 (A row)
    const int lq = (tid & 3) * 4;        // 0..12 (A k offset, float4)
    const int lk = tid >> 4;             // 0..15 (B row)
    const int ln = (tid & 15) * 4;       // 0..60 (B col, float4)

    float acc[4][4];
#pragma unroll
    for (int i = 0; i < 4; i++)
#pragma unroll
        for (int j = 0; j < 4; j++) acc[i][j] = 0.f;

    for (int k0 = 0; k0 < K; k0 += 16) {
        float4 a4 = *reinterpret_cast<const float4*>(&A[(size_t)(m0 + lm) * K + k0 + lq]);
        As[lq + 0][lm] = a4.x;
        As[lq + 1][lm] = a4.y;
        As[lq + 2][lm] = a4.z;
        As[lq + 3][lm] = a4.w;
        *reinterpret_cast<float4*>(&Bs[lk][ln]) =
            *reinterpret_cast<const float4*>(&Bm[(size_t)(k0 + lk) * N + n0 + ln]);
        __syncthreads();

#pragma unroll
        for (int kk = 0; kk < 16; kk++) {
            float ra[4];
#pragma unroll
            for (int i = 0; i < 4; i++) ra[i] = As[kk][ty * 4 + i];
            float4 b4 = *reinterpret_cast<const float4*>(&Bs[kk][tx * 4]);
            float rb[4] = {b4.x, b4.y, b4.z, b4.w};
#pragma unroll
            for (int i = 0; i < 4; i++)
#pragma unroll
                for (int j = 0; j < 4; j++) acc[i][j] = fmaf(ra[i], rb[j], acc[i][j]);
        }
        __syncthreads();
    }

#pragma unroll
    for (int i = 0; i < 4; i++) {
        float4 o4 = make_float4(acc[i][0], acc[i][1], acc[i][2], acc[i][3]);
        *reinterpret_cast<float4*>(&C[(size_t)(m0 + ty * 4 + i) * N + n0 + tx * 4]) = o4;
    }
}

// ---------------------------------------------------------------------------
// RoPE applied in-place to q and k slices of g_qkv.
// One thread per (b,t,h,pair). ang repeated -> cos[2i]==cos[2i+1].
// out[2i]   = x[2i]*c - x[2i+1]*s
// out[2i+1] = x[2i+1]*c + x[2i]*s
// ---------------------------------------------------------------------------
__global__ __launch_bounds__(256) void rope_kernel(const float* __restrict__ sin_t,
                                                   const float* __restrict__ cos_t) {
    const int idx = blockIdx.x * blockDim.x + threadIdx.x;   // 0 .. B*T*NH*32-1
    const int total = B_ * T_ * NH_ * (HD_ / 2);
    if (idx >= total) return;
    const int i = idx & 31;                // pair index within head
    const int h = (idx >> 5) & (NH_ - 1);
    const int bt = idx >> 9;               // b*T + t
    const int t = bt & (T_ - 1);

    const float s = sin_t[t * HD_ + 2 * i];
    const float c = cos_t[t * HD_ + 2 * i];

    float* row = g_qkv + (size_t)bt * (3 * DIM_);
    float* q = row + h * HD_ + 2 * i;
    float q1 = q[0], q2 = q[1];
    q[0] = q1 * c - q2 * s;
    q[1] = q2 * c + q1 * s;

    float* k = row + DIM_ + h * HD_ + 2 * i;
    float k1 = k[0], k2 = k[1];
    k[0] = k1 * c - k2 * s;
    k[1] = k2 * c + k1 * s;
}

// ---------------------------------------------------------------------------
// Flash attention (causal), fp32. One block per (q-tile, head, batch).
// BQ=BK=64, HD=64. 256 threads, 4x4 register tiles.
// smem stride 65 to avoid bank conflicts.
// ---------------------------------------------------------------------------
#define FA_STRIDE 65
#define FA_SMEM_FLOATS (4 * 64 * FA_STRIDE)

__global__ __launch_bounds__(256) void flash_kernel(float* __restrict__ y) {
    extern __shared__ float sm[];
    float* Qs = sm;                         // [64][65]
    float* Ks = Qs + 64 * FA_STRIDE;
    float* Vs = Ks + 64 * FA_STRIDE;
    float* Ps = Vs + 64 * FA_STRIDE;

    const int tid = threadIdx.x;
    const int ty = tid >> 4;    // 0..15 -> rows ty*4..ty*4+3
    const int tx = tid & 15;    // 0..15 -> cols tx*4..tx*4+3

    const int qt = blockIdx.x;          // q tile index (0..31)
    const int h  = blockIdx.y;
    const int b  = blockIdx.z;
    const int q0 = qt * 64;

    // load indices for tile loads: 64 rows x 64 cols, 256 threads,
    // each thread loads 16 consecutive floats (4 x float4) of one row.
    const int lrow = tid >> 2;            // 0..63
    const int lcol = (tid & 3) * 16;      // 0,16,32,48

    const float* qkv = g_qkv;
    const size_t rowstride = 3 * DIM_;

    // Load Q tile once
    {
        const float* src = qkv + ((size_t)(b * T_ + q0 + lrow)) * rowstride + h * HD_;
#pragma unroll
        for (int v = 0; v < 4; v++) {
            float4 x4 = *reinterpret_cast<const float4*>(src + lcol + v * 4);
            float* dst = &Qs[lrow * FA_STRIDE + lcol + v * 4];
            dst[0] = x4.x; dst[1] = x4.y; dst[2] = x4.z; dst[3] = x4.w;
        }
    }

    float m_i[4], l_i[4], o[4][4];
#pragma unroll
    for (int i = 0; i < 4; i++) {
        m_i[i] = -INFINITY;
        l_i[i] = 0.f;
#pragma unroll
        for (int j = 0; j < 4; j++) o[i][j] = 0.f;
    }

    const float scale = 0.125f;   // 1/sqrt(64)

    for (int kt = 0; kt <= qt; kt++) {
        const int k0 = kt * 64;
        __syncthreads();   // previous P@V done: safe to overwrite Ks/Vs

        // load K and V tiles
        {
            const float* ksrc = qkv + ((size_t)(b * T_ + k0 + lrow)) * rowstride + DIM_ + h * HD_;
            const float* vsrc = ksrc + DIM_;
#pragma unroll
            for (int v = 0; v < 4; v++) {
                float4 x4 = *reinterpret_cast<const float4*>(ksrc + lcol + v * 4);
                float* dst = &Ks[lrow * FA_STRIDE + lcol + v * 4];
                dst[0] = x4.x; dst[1] = x4.y; dst[2] = x4.z; dst[3] = x4.w;
                float4 y4 = *reinterpret_cast<const float4*>(vsrc + lcol + v * 4);
                float* dv = &Vs[lrow * FA_STRIDE + lcol + v * 4];
                dv[0] = y4.x; dv[1] = y4.y; dv[2] = y4.z; dv[3] = y4.w;
            }
        }
        __syncthreads();   // tiles ready

        // S = Q @ K^T (4x4 per thread)
        float s[4][4];
#pragma unroll
        for (int i = 0; i < 4; i++)
#pragma unroll
            for (int j = 0; j < 4; j++) s[i][j] = 0.f;

        for (int d = 0; d < 64; d++) {
            float ra[4], rk[4];
#pragma unroll
            for (int i = 0; i < 4; i++) ra[i] = Qs[(ty * 4 + i) * FA_STRIDE + d];
#pragma unroll
            for (int j = 0; j < 4; j++) rk[j] = Ks[(tx * 4 + j) * FA_STRIDE + d];
#pragma unroll
            for (int i = 0; i < 4; i++)
#pragma unroll
                for (int j = 0; j < 4; j++) s[i][j] = fmaf(ra[i], rk[j], s[i][j]);
        }

        // scale + causal mask (diagonal tile only)
#pragma unroll
        for (int i = 0; i < 4; i++)
#pragma unroll
            for (int j = 0; j < 4; j++) {
                s[i][j] *= scale;
                if (kt == qt && (tx * 4 + j) > (ty * 4 + i)) s[i][j] = -1e30f;
            }

        // row stats + flash update
#pragma unroll
        for (int i = 0; i < 4; i++) {
            float mloc = fmaxf(fmaxf(s[i][0], s[i][1]), fmaxf(s[i][2], s[i][3]));
#pragma unroll
            for (int off = 8; off > 0; off >>= 1)
                mloc = fmaxf(mloc, __shfl_xor_sync(0xffffffffu, mloc, off, 16));
            float m_new = fmaxf(m_i[i], mloc);
            float alpha = __expf(m_i[i] - m_new);
            float rs = 0.f;
#pragma unroll
            for (int j = 0; j < 4; j++) {
                float p = __expf(s[i][j] - m_new);
                s[i][j] = p;
                rs += p;
            }
#pragma unroll
            for (int off = 8; off > 0; off >>= 1)
                rs += __shfl_xor_sync(0xffffffffu, rs, off, 16);
            l_i[i] = l_i[i] * alpha + rs;
            m_i[i] = m_new;
#pragma unroll
            for (int j = 0; j < 4; j++) o[i][j] *= alpha;
        }

        // write P
#pragma unroll
        for (int i = 0; i < 4; i++)
#pragma unroll
            for (int j = 0; j < 4; j++)
                Ps[(ty * 4 + i) * FA_STRIDE + tx * 4 + j] = s[i][j];
        __syncthreads();   // Ps ready

        // O += P @ V
        for (int k = 0; k < 64; k++) {
            float rp[4], rv[4];
#pragma unroll
            for (int i = 0; i < 4; i++) rp[i] = Ps[(ty * 4 + i) * FA_STRIDE + k];
#pragma unroll
            for (int j = 0; j < 4; j++) rv[j] = Vs[k * FA_STRIDE + tx * 4 + j];
#pragma unroll
            for (int i = 0; i < 4; i++)
#pragma unroll
                for (int j = 0; j < 4; j++) o[i][j] = fmaf(rp[i], rv[j], o[i][j]);
        }
    }

    // write output: y[b, q0+r, h*64 + c] = o / l
#pragma unroll
    for (int i = 0; i < 4; i++) {
        float inv = 1.0f / l_i[i];
        float4 o4 = make_float4(o[i][0] * inv, o[i][1] * inv, o[i][2] * inv, o[i][3] * inv);
        *reinterpret_cast<float4*>(
            &y[((size_t)(b * T_ + q0 + ty * 4 + i)) * DIM_ + h * HD_ + tx * 4]) = o4;
    }
}

// ---------------------------------------------------------------------------
// Launch
// ---------------------------------------------------------------------------
extern "C" void kernel_launch(void* const* d_in, const int* in_sizes, int n_in,
                              void* d_out, int out_size) {
    const float* x      = (const float*)d_in[0];   // [B,T,DIM]
    const float* sin_t  = (const float*)d_in[1];   // [1,1,T,HD]
    const float* cos_t  = (const float*)d_in[2];   // [1,1,T,HD]
    const float* W_qkv  = (const float*)d_in[3];   // [DIM, 3*DIM]
    const float* W_proj = (const float*)d_in[4];   // [DIM, DIM]
    float* out = (float*)d_out;                    // [B,T,DIM]

    float* qkv_ptr = nullptr;
    float* y_ptr = nullptr;
    cudaGetSymbolAddress((void**)&qkv_ptr, g_qkv);
    cudaGetSymbolAddress((void**)&y_ptr, g_y);

    const int M = B_ * T_;        // 4096

    // 1) QKV GEMM: [4096,1024] @ [1024,3072]
    {
        dim3 grid((3 * DIM_) / 64, M / 64);
        sgemm64<<<grid, 256>>>(x, W_qkv, qkv_ptr, M, 3 * DIM_, DIM_);
    }

    // 2) RoPE on q,k
    {
        int total = B_ * T_ * NH_ * (HD_ / 2);
        rope_kernel<<<(total + 255) / 256, 256>>>(sin_t, cos_t);
    }

    // 3) Flash attention
    {
        int smem_bytes = FA_SMEM_FLOATS * (int)sizeof(float);   // 66,560
        cudaFuncSetAttribute(flash_kernel, cudaFuncAttributeMaxDynamicSharedMemorySize,
                             smem_bytes);
        dim3 grid(T_ / 64, NH_, B_);
        flash_kernel<<<grid, 256, smem_bytes>>>(y_ptr);
    }

    // 4) Output projection: [4096,1024] @ [1024,1024]
    {
        dim3 grid(DIM_ / 64, M / 64);
        sgemm64<<<grid, 256>>>(y_ptr, W_proj, out, M, DIM_, DIM_);
    }
}

// round 2
// speedup vs baseline: 1.1719x; 1.1719x over previous
#include <cuda_runtime.h>
#include <cuda_bf16.h>
#include <math.h>
#include <stdint.h>

#define B_   2
#define T_   2048
#define DIM_ 1024
#define NH_  16
#define HD_  64

// Scratch (alloc-free rule: __device__ globals)
__device__ float g_qkv[(size_t)B_ * T_ * 3 * DIM_];   // [B,T, 3*DIM] : q|k|v
__device__ float g_y  [(size_t)B_ * T_ * DIM_];       // attention output [B,T,DIM]

// ===========================================================================
// bf16x3 tensor-core GEMM: C[M,N] = A[M,K] @ B[K,N] (row-major, fp32 in/out)
// Split each fp32 operand into hi+lo bf16; D += AhiBhi + AhiBlo + AloBhi.
// Block tile 128x64, BK=32, 256 threads (8 warps: 4 M x 2 N),
// warp tile 32x32 = 2 (m16) x 4 (n8) mma tiles.
// ===========================================================================
#define BM 128
#define BN 64
#define BK 32
#define SA_STRIDE 20   // uint32 stride per A row: (BK + 8 pad)/2
#define SB_STRIDE 20   // uint32 stride per B(n) row

__device__ __forceinline__ void mma_bf16(float c[4], const uint32_t a[4],
                                         const uint32_t b[2]) {
    asm volatile(
        "mma.sync.aligned.m16n8k16.row.col.f32.bf16.bf16.f32 "
        "{%0,%1,%2,%3}, {%4,%5,%6,%7}, {%8,%9}, {%0,%1,%2,%3};\n"
        : "+f"(c[0]), "+f"(c[1]), "+f"(c[2]), "+f"(c[3])
        : "r"(a[0]), "r"(a[1]), "r"(a[2]), "r"(a[3]), "r"(b[0]), "r"(b[1]));
}

__global__ __launch_bounds__(256) void gemm_bf16x3(const float* __restrict__ A,
                                                   const float* __restrict__ Bm,
                                                   float* __restrict__ C,
                                                   int M, int N, int K) {
    __shared__ uint32_t sAhi[BM * SA_STRIDE];
    __shared__ uint32_t sAlo[BM * SA_STRIDE];
    __shared__ uint32_t sBhi[BN * SB_STRIDE];
    __shared__ uint32_t sBlo[BN * SB_STRIDE];

    const int tid  = threadIdx.x;
    const int lane = tid & 31;
    const int wid  = tid >> 5;
    const int wm   = wid & 3;         // 0..3 -> M offset wm*32
    const int wn   = wid >> 2;        // 0..1 -> N offset wn*32
    const int lr   = lane >> 2;       // 0..7
    const int lc   = lane & 3;        // 0..3

    const int m0 = blockIdx.y * BM;
    const int n0 = blockIdx.x * BN;

    // A load mapping: row = tid>>1 (0..127), 16 cols starting at (tid&1)*16
    const int a_row = tid >> 1;
    const int a_cg  = (tid & 1) * 16;
    // B load mapping: k row = tid>>3 (0..31), 8 cols starting at (tid&7)*8
    const int b_k   = tid >> 3;
    const int b_n0  = (tid & 7) * 8;

    float acc[2][4][4];
#pragma unroll
    for (int mt = 0; mt < 2; mt++)
#pragma unroll
        for (int nt = 0; nt < 4; nt++)
#pragma unroll
            for (int j = 0; j < 4; j++) acc[mt][nt][j] = 0.f;

    __nv_bfloat16* sBhi_h = reinterpret_cast<__nv_bfloat16*>(sBhi);
    __nv_bfloat16* sBlo_h = reinterpret_cast<__nv_bfloat16*>(sBlo);

    for (int k0 = 0; k0 < K; k0 += BK) {
        // ---- load A tile (128x32), split hi/lo, pack k-pairs ----
#pragma unroll
        for (int v = 0; v < 4; v++) {
            float4 a4 = *reinterpret_cast<const float4*>(
                &A[(size_t)(m0 + a_row) * K + k0 + a_cg + v * 4]);
            float f[4] = {a4.x, a4.y, a4.z, a4.w};
            __nv_bfloat16 h[4], l[4];
#pragma unroll
            for (int e = 0; e < 4; e++) {
                h[e] = __float2bfloat16_rn(f[e]);
                l[e] = __float2bfloat16_rn(f[e] - __bfloat162float(h[e]));
            }
            const int pi = (a_cg >> 1) + v * 2;     // pair index
            __nv_bfloat162 hp0 = {h[0], h[1]}, hp1 = {h[2], h[3]};
            __nv_bfloat162 lp0 = {l[0], l[1]}, lp1 = {l[2], l[3]};
            sAhi[a_row * SA_STRIDE + pi + 0] = *reinterpret_cast<uint32_t*>(&hp0);
            sAhi[a_row * SA_STRIDE + pi + 1] = *reinterpret_cast<uint32_t*>(&hp1);
            sAlo[a_row * SA_STRIDE + pi + 0] = *reinterpret_cast<uint32_t*>(&lp0);
            sAlo[a_row * SA_STRIDE + pi + 1] = *reinterpret_cast<uint32_t*>(&lp1);
        }
        // ---- load B tile (32x64), transpose into [n][k] bf16, split hi/lo ----
#pragma unroll
        for (int v = 0; v < 2; v++) {
            float4 b4 = *reinterpret_cast<const float4*>(
                &Bm[(size_t)(k0 + b_k) * N + n0 + b_n0 + v * 4]);
            float f[4] = {b4.x, b4.y, b4.z, b4.w};
#pragma unroll
            for (int e = 0; e < 4; e++) {
                __nv_bfloat16 h = __float2bfloat16_rn(f[e]);
                __nv_bfloat16 l = __float2bfloat16_rn(f[e] - __bfloat162float(h));
                const int n = b_n0 + v * 4 + e;
                sBhi_h[n * (2 * SB_STRIDE) + b_k] = h;
                sBlo_h[n * (2 * SB_STRIDE) + b_k] = l;
            }
        }
        __syncthreads();

        // ---- compute: 2 k16 steps ----
#pragma unroll
        for (int ks = 0; ks < 2; ks++) {
            uint32_t ahi[2][4], alo[2][4];
#pragma unroll
            for (int mt = 0; mt < 2; mt++) {
                const int r = wm * 32 + mt * 16 + lr;
                const int base = ks * 8 + lc;
                ahi[mt][0] = sAhi[r * SA_STRIDE + base];
                ahi[mt][1] = sAhi[(r + 8) * SA_STRIDE + base];
                ahi[mt][2] = sAhi[r * SA_STRIDE + base + 4];
                ahi[mt][3] = sAhi[(r + 8) * SA_STRIDE + base + 4];
                alo[mt][0] = sAlo[r * SA_STRIDE + base];
                alo[mt][1] = sAlo[(r + 8) * SA_STRIDE + base];
                alo[mt][2] = sAlo[r * SA_STRIDE + base + 4];
                alo[mt][3] = sAlo[(r + 8) * SA_STRIDE + base + 4];
            }
            uint32_t bhi[4][2], blo[4][2];
#pragma unroll
            for (int nt = 0; nt < 4; nt++) {
                const int n = wn * 32 + nt * 8 + lr;
                const int base = ks * 8 + lc;
                bhi[nt][0] = sBhi[n * SB_STRIDE + base];
                bhi[nt][1] = sBhi[n * SB_STRIDE + base + 4];
                blo[nt][0] = sBlo[n * SB_STRIDE + base];
                blo[nt][1] = sBlo[n * SB_STRIDE + base + 4];
            }
#pragma unroll
            for (int mt = 0; mt < 2; mt++)
#pragma unroll
                for (int nt = 0; nt < 4; nt++) {
                    mma_bf16(acc[mt][nt], ahi[mt], bhi[nt]);
                    mma_bf16(acc[mt][nt], ahi[mt], blo[nt]);
                    mma_bf16(acc[mt][nt], alo[mt], bhi[nt]);
                }
        }
        __syncthreads();
    }

    // ---- epilogue ----
#pragma unroll
    for (int mt = 0; mt < 2; mt++) {
#pragma unroll
        for (int nt = 0; nt < 4; nt++) {
            const int row0 = m0 + wm * 32 + mt * 16 + lr;
            const int col  = n0 + wn * 32 + nt * 8 + lc * 2;
            float2 v0 = make_float2(acc[mt][nt][0], acc[mt][nt][1]);
            float2 v1 = make_float2(acc[mt][nt][2], acc[mt][nt][3]);
            *reinterpret_cast<float2*>(&C[(size_t)row0 * N + col]) = v0;
            *reinterpret_cast<float2*>(&C[(size_t)(row0 + 8) * N + col]) = v1;
        }
    }
}

// ---------------------------------------------------------------------------
// RoPE applied in-place to q and k slices of g_qkv.
// ---------------------------------------------------------------------------
__global__ __launch_bounds__(256) void rope_kernel(const float* __restrict__ sin_t,
                                                   const float* __restrict__ cos_t) {
    const int idx = blockIdx.x * blockDim.x + threadIdx.x;
    const int total = B_ * T_ * NH_ * (HD_ / 2);
    if (idx >= total) return;
    const int i = idx & 31;
    const int h = (idx >> 5) & (NH_ - 1);
    const int bt = idx >> 9;
    const int t = bt & (T_ - 1);

    const float s = sin_t[t * HD_ + 2 * i];
    const float c = cos_t[t * HD_ + 2 * i];

    float* row = g_qkv + (size_t)bt * (3 * DIM_);
    float* q = row + h * HD_ + 2 * i;
    float q1 = q[0], q2 = q[1];
    q[0] = q1 * c - q2 * s;
    q[1] = q2 * c + q1 * s;

    float* k = row + DIM_ + h * HD_ + 2 * i;
    float k1 = k[0], k2 = k[1];
    k[0] = k1 * c - k2 * s;
    k[1] = k2 * c + k1 * s;
}

// ---------------------------------------------------------------------------
// Flash attention (causal), fp32 (unchanged from R1).
// ---------------------------------------------------------------------------
#define FA_STRIDE 65
#define FA_SMEM_FLOATS (4 * 64 * FA_STRIDE)

__global__ __launch_bounds__(256) void flash_kernel(float* __restrict__ y) {
    extern __shared__ float sm[];
    float* Qs = sm;
    float* Ks = Qs + 64 * FA_STRIDE;
    float* Vs = Ks + 64 * FA_STRIDE;
    float* Ps = Vs + 64 * FA_STRIDE;

    const int tid = threadIdx.x;
    const int ty = tid >> 4;
    const int tx = tid & 15;

    const int qt = blockIdx.x;
    const int h  = blockIdx.y;
    const int b  = blockIdx.z;
    const int q0 = qt * 64;

    const int lrow = tid >> 2;
    const int lcol = (tid & 3) * 16;

    const float* qkv = g_qkv;
    const size_t rowstride = 3 * DIM_;

    {
        const float* src = qkv + ((size_t)(b * T_ + q0 + lrow)) * rowstride + h * HD_;
#pragma unroll
        for (int v = 0; v < 4; v++) {
            float4 x4 = *reinterpret_cast<const float4*>(src + lcol + v * 4);
            float* dst = &Qs[lrow * FA_STRIDE + lcol + v * 4];
            dst[0] = x4.x; dst[1] = x4.y; dst[2] = x4.z; dst[3] = x4.w;
        }
    }

    float m_i[4], l_i[4], o[4][4];
#pragma unroll
    for (int i = 0; i < 4; i++) {
        m_i[i] = -INFINITY;
        l_i[i] = 0.f;
#pragma unroll
        for (int j = 0; j < 4; j++) o[i][j] = 0.f;
    }

    const float scale = 0.125f;

    for (int kt = 0; kt <= qt; kt++) {
        const int k0 = kt * 64;
        __syncthreads();

        {
            const float* ksrc = qkv + ((size_t)(b * T_ + k0 + lrow)) * rowstride + DIM_ + h * HD_;
            const float* vsrc = ksrc + DIM_;
#pragma unroll
            for (int v = 0; v < 4; v++) {
                float4 x4 = *reinterpret_cast<const float4*>(ksrc + lcol + v * 4);
                float* dst = &Ks[lrow * FA_STRIDE + lcol + v * 4];
                dst[0] = x4.x; dst[1] = x4.y; dst[2] = x4.z; dst[3] = x4.w;
                float4 y4 = *reinterpret_cast<const float4*>(vsrc + lcol + v * 4);
                float* dv = &Vs[lrow * FA_STRIDE + lcol + v * 4];
                dv[0] = y4.x; dv[1] = y4.y; dv[2] = y4.z; dv[3] = y4.w;
            }
        }
        __syncthreads();

        float s[4][4];
#pragma unroll
        for (int i = 0; i < 4; i++)
#pragma unroll
            for (int j = 0; j < 4; j++) s[i][j] = 0.f;

        for (int d = 0; d < 64; d++) {
            float ra[4], rk[4];
#pragma unroll
            for (int i = 0; i < 4; i++) ra[i] = Qs[(ty * 4 + i) * FA_STRIDE + d];
#pragma unroll
            for (int j = 0; j < 4; j++) rk[j] = Ks[(tx * 4 + j) * FA_STRIDE + d];
#pragma unroll
            for (int i = 0; i < 4; i++)
#pragma unroll
                for (int j = 0; j < 4; j++) s[i][j] = fmaf(ra[i], rk[j], s[i][j]);
        }

#pragma unroll
        for (int i = 0; i < 4; i++)
#pragma unroll
            for (int j = 0; j < 4; j++) {
                s[i][j] *= scale;
                if (kt == qt && (tx * 4 + j) > (ty * 4 + i)) s[i][j] = -1e30f;
            }

#pragma unroll
        for (int i = 0; i < 4; i++) {
            float mloc = fmaxf(fmaxf(s[i][0], s[i][1]), fmaxf(s[i][2], s[i][3]));
#pragma unroll
            for (int off = 8; off > 0; off >>= 1)
                mloc = fmaxf(mloc, __shfl_xor_sync(0xffffffffu, mloc, off, 16));
            float m_new = fmaxf(m_i[i], mloc);
            float alpha = __expf(m_i[i] - m_new);
            float rs = 0.f;
#pragma unroll
            for (int j = 0; j < 4; j++) {
                float p = __expf(s[i][j] - m_new);
                s[i][j] = p;
                rs += p;
            }
#pragma unroll
            for (int off = 8; off > 0; off >>= 1)
                rs += __shfl_xor_sync(0xffffffffu, rs, off, 16);
            l_i[i] = l_i[i] * alpha + rs;
            m_i[i] = m_new;
#pragma unroll
            for (int j = 0; j < 4; j++) o[i][j] *= alpha;
        }

#pragma unroll
        for (int i = 0; i < 4; i++)
#pragma unroll
            for (int j = 0; j < 4; j++)
                Ps[(ty * 4 + i) * FA_STRIDE + tx * 4 + j] = s[i][j];
        __syncthreads();

        for (int k = 0; k < 64; k++) {
            float rp[4], rv[4];
#pragma unroll
            for (int i = 0; i < 4; i++) rp[i] = Ps[(ty * 4 + i) * FA_STRIDE + k];
#pragma unroll
            for (int j = 0; j < 4; j++) rv[j] = Vs[k * FA_STRIDE + tx * 4 + j];
#pragma unroll
            for (int i = 0; i < 4; i++)
#pragma unroll
                for (int j = 0; j < 4; j++) o[i][j] = fmaf(rp[i], rv[j], o[i][j]);
        }
    }

#pragma unroll
    for (int i = 0; i < 4; i++) {
        float inv = 1.0f / l_i[i];
        float4 o4 = make_float4(o[i][0] * inv, o[i][1] * inv, o[i][2] * inv, o[i][3] * inv);
        *reinterpret_cast<float4*>(
            &y[((size_t)(b * T_ + q0 + ty * 4 + i)) * DIM_ + h * HD_ + tx * 4]) = o4;
    }
}

// ---------------------------------------------------------------------------
// Launch
// ---------------------------------------------------------------------------
extern "C" void kernel_launch(void* const* d_in, const int* in_sizes, int n_in,
                              void* d_out, int out_size) {
    const float* x      = (const float*)d_in[0];
    const float* sin_t  = (const float*)d_in[1];
    const float* cos_t  = (const float*)d_in[2];
    const float* W_qkv  = (const float*)d_in[3];
    const float* W_proj = (const float*)d_in[4];
    float* out = (float*)d_out;

    float* qkv_ptr = nullptr;
    float* y_ptr = nullptr;
    cudaGetSymbolAddress((void**)&qkv_ptr, g_qkv);
    cudaGetSymbolAddress((void**)&y_ptr, g_y);

    const int M = B_ * T_;   // 4096

    // 1) QKV GEMM: [4096,1024] @ [1024,3072] (bf16x3 tensor core)
    {
        dim3 grid((3 * DIM_) / BN, M / BM);
        gemm_bf16x3<<<grid, 256>>>(x, W_qkv, qkv_ptr, M, 3 * DIM_, DIM_);
    }

    // 2) RoPE on q,k
    {
        int total = B_ * T_ * NH_ * (HD_ / 2);
        rope_kernel<<<(total + 255) / 256, 256>>>(sin_t, cos_t);
    }

    // 3) Flash attention
    {
        int smem_bytes = FA_SMEM_FLOATS * (int)sizeof(float);
        cudaFuncSetAttribute(flash_kernel, cudaFuncAttributeMaxDynamicSharedMemorySize,
                             smem_bytes);
        dim3 grid(T_ / 64, NH_, B_);
        flash_kernel<<<grid, 256, smem_bytes>>>(y_ptr);
    }

    // 4) Output projection: [4096,1024] @ [1024,1024]
    {
        dim3 grid(DIM_ / BN, M / BM);
        gemm_bf16x3<<<grid, 256>>>(y_ptr, W_proj, out, M, DIM_, DIM_);
    }
}

// round 3
// speedup vs baseline: 1.5292x; 1.3048x over previous
#include <cuda_runtime.h>
#include <cuda_bf16.h>
#include <math.h>
#include <stdint.h>

#define B_   2
#define T_   2048
#define DIM_ 1024
#define NH_  16
#define HD_  64

__device__ float g_qkv[(size_t)B_ * T_ * 3 * DIM_];
__device__ float g_y  [(size_t)B_ * T_ * DIM_];

__device__ __forceinline__ void mma_bf16(float c[4], const uint32_t a[4],
                                         const uint32_t b[2]) {
    asm volatile(
        "mma.sync.aligned.m16n8k16.row.col.f32.bf16.bf16.f32 "
        "{%0,%1,%2,%3}, {%4,%5,%6,%7}, {%8,%9}, {%0,%1,%2,%3};\n"
        : "+f"(c[0]), "+f"(c[1]), "+f"(c[2]), "+f"(c[3])
        : "r"(a[0]), "r"(a[1]), "r"(a[2]), "r"(a[3]), "r"(b[0]), "r"(b[1]));
}

__device__ __forceinline__ uint32_t pack_hi2(float x, float y) {
    __nv_bfloat162 p = {__float2bfloat16_rn(x), __float2bfloat16_rn(y)};
    return *reinterpret_cast<uint32_t*>(&p);
}
__device__ __forceinline__ uint32_t pack_lo2(float x, float y) {
    float xh = __bfloat162float(__float2bfloat16_rn(x));
    float yh = __bfloat162float(__float2bfloat16_rn(y));
    __nv_bfloat162 p = {__float2bfloat16_rn(x - xh), __float2bfloat16_rn(y - yh)};
    return *reinterpret_cast<uint32_t*>(&p);
}

// ===========================================================================
// bf16x3 tensor-core GEMM (unchanged from R2)
// ===========================================================================
#define BM 128
#define BN 64
#define BK 32
#define SA_STRIDE 20
#define SB_STRIDE 20

__global__ __launch_bounds__(256) void gemm_bf16x3(const float* __restrict__ A,
                                                   const float* __restrict__ Bm,
                                                   float* __restrict__ C,
                                                   int M, int N, int K) {
    __shared__ uint32_t sAhi[BM * SA_STRIDE];
    __shared__ uint32_t sAlo[BM * SA_STRIDE];
    __shared__ uint32_t sBhi[BN * SB_STRIDE];
    __shared__ uint32_t sBlo[BN * SB_STRIDE];

    const int tid  = threadIdx.x;
    const int lane = tid & 31;
    const int wid  = tid >> 5;
    const int wm   = wid & 3;
    const int wn   = wid >> 2;
    const int lr   = lane >> 2;
    const int lc   = lane & 3;

    const int m0 = blockIdx.y * BM;
    const int n0 = blockIdx.x * BN;

    const int a_row = tid >> 1;
    const int a_cg  = (tid & 1) * 16;
    const int b_k   = tid >> 3;
    const int b_n0  = (tid & 7) * 8;

    float acc[2][4][4];
#pragma unroll
    for (int mt = 0; mt < 2; mt++)
#pragma unroll
        for (int nt = 0; nt < 4; nt++)
#pragma unroll
            for (int j = 0; j < 4; j++) acc[mt][nt][j] = 0.f;

    __nv_bfloat16* sBhi_h = reinterpret_cast<__nv_bfloat16*>(sBhi);
    __nv_bfloat16* sBlo_h = reinterpret_cast<__nv_bfloat16*>(sBlo);

    for (int k0 = 0; k0 < K; k0 += BK) {
#pragma unroll
        for (int v = 0; v < 4; v++) {
            float4 a4 = *reinterpret_cast<const float4*>(
                &A[(size_t)(m0 + a_row) * K + k0 + a_cg + v * 4]);
            const int pi = (a_cg >> 1) + v * 2;
            sAhi[a_row * SA_STRIDE + pi + 0] = pack_hi2(a4.x, a4.y);
            sAhi[a_row * SA_STRIDE + pi + 1] = pack_hi2(a4.z, a4.w);
            sAlo[a_row * SA_STRIDE + pi + 0] = pack_lo2(a4.x, a4.y);
            sAlo[a_row * SA_STRIDE + pi + 1] = pack_lo2(a4.z, a4.w);
        }
#pragma unroll
        for (int v = 0; v < 2; v++) {
            float4 b4 = *reinterpret_cast<const float4*>(
                &Bm[(size_t)(k0 + b_k) * N + n0 + b_n0 + v * 4]);
            float f[4] = {b4.x, b4.y, b4.z, b4.w};
#pragma unroll
            for (int e = 0; e < 4; e++) {
                __nv_bfloat16 h = __float2bfloat16_rn(f[e]);
                __nv_bfloat16 l = __float2bfloat16_rn(f[e] - __bfloat162float(h));
                const int n = b_n0 + v * 4 + e;
                sBhi_h[n * (2 * SB_STRIDE) + b_k] = h;
                sBlo_h[n * (2 * SB_STRIDE) + b_k] = l;
            }
        }
        __syncthreads();

#pragma unroll
        for (int ks = 0; ks < 2; ks++) {
            uint32_t ahi[2][4], alo[2][4];
#pragma unroll
            for (int mt = 0; mt < 2; mt++) {
                const int r = wm * 32 + mt * 16 + lr;
                const int base = ks * 8 + lc;
                ahi[mt][0] = sAhi[r * SA_STRIDE + base];
                ahi[mt][1] = sAhi[(r + 8) * SA_STRIDE + base];
                ahi[mt][2] = sAhi[r * SA_STRIDE + base + 4];
                ahi[mt][3] = sAhi[(r + 8) * SA_STRIDE + base + 4];
                alo[mt][0] = sAlo[r * SA_STRIDE + base];
                alo[mt][1] = sAlo[(r + 8) * SA_STRIDE + base];
                alo[mt][2] = sAlo[r * SA_STRIDE + base + 4];
                alo[mt][3] = sAlo[(r + 8) * SA_STRIDE + base + 4];
            }
            uint32_t bhi[4][2], blo[4][2];
#pragma unroll
            for (int nt = 0; nt < 4; nt++) {
                const int n = wn * 32 + nt * 8 + lr;
                const int base = ks * 8 + lc;
                bhi[nt][0] = sBhi[n * SB_STRIDE + base];
                bhi[nt][1] = sBhi[n * SB_STRIDE + base + 4];
                blo[nt][0] = sBlo[n * SB_STRIDE + base];
                blo[nt][1] = sBlo[n * SB_STRIDE + base + 4];
            }
#pragma unroll
            for (int mt = 0; mt < 2; mt++)
#pragma unroll
                for (int nt = 0; nt < 4; nt++) {
                    mma_bf16(acc[mt][nt], ahi[mt], bhi[nt]);
                    mma_bf16(acc[mt][nt], ahi[mt], blo[nt]);
                    mma_bf16(acc[mt][nt], alo[mt], bhi[nt]);
                }
        }
        __syncthreads();
    }

#pragma unroll
    for (int mt = 0; mt < 2; mt++) {
#pragma unroll
        for (int nt = 0; nt < 4; nt++) {
            const int row0 = m0 + wm * 32 + mt * 16 + lr;
            const int col  = n0 + wn * 32 + nt * 8 + lc * 2;
            float2 v0 = make_float2(acc[mt][nt][0], acc[mt][nt][1]);
            float2 v1 = make_float2(acc[mt][nt][2], acc[mt][nt][3]);
            *reinterpret_cast<float2*>(&C[(size_t)row0 * N + col]) = v0;
            *reinterpret_cast<float2*>(&C[(size_t)(row0 + 8) * N + col]) = v1;
        }
    }
}

// ---------------------------------------------------------------------------
// RoPE (unchanged)
// ---------------------------------------------------------------------------
__global__ __launch_bounds__(256) void rope_kernel(const float* __restrict__ sin_t,
                                                   const float* __restrict__ cos_t) {
    const int idx = blockIdx.x * blockDim.x + threadIdx.x;
    const int total = B_ * T_ * NH_ * (HD_ / 2);
    if (idx >= total) return;
    const int i = idx & 31;
    const int h = (idx >> 5) & (NH_ - 1);
    const int bt = idx >> 9;
    const int t = bt & (T_ - 1);

    const float s = sin_t[t * HD_ + 2 * i];
    const float c = cos_t[t * HD_ + 2 * i];

    float* row = g_qkv + (size_t)bt * (3 * DIM_);
    float* q = row + h * HD_ + 2 * i;
    float q1 = q[0], q2 = q[1];
    q[0] = q1 * c - q2 * s;
    q[1] = q2 * c + q1 * s;

    float* k = row + DIM_ + h * HD_ + 2 * i;
    float k1 = k[0], k2 = k[1];
    k[0] = k1 * c - k2 * s;
    k[1] = k2 * c + k1 * s;
}

// ===========================================================================
// Flash attention with tensor-core MMA (bf16x3), causal.
// 128 threads = 4 warps; each warp owns 16 q-rows. BQ=BK=64, HD=64.
// smem: Q/K as [row][d-pair] uint32 stride 36; V transposed [d][key-pair].
// ===========================================================================
#define FS 36   // uint32 stride per 64-wide bf16 row (32 pairs + 4 pad)
#define FA_SMEM_BYTES (6 * 64 * FS * 4)

__global__ __launch_bounds__(128) void flash_mma(float* __restrict__ y) {
    extern __shared__ uint32_t sm[];
    uint32_t* Qhi = sm;
    uint32_t* Qlo = Qhi + 64 * FS;
    uint32_t* Khi = Qlo + 64 * FS;
    uint32_t* Klo = Khi + 64 * FS;
    uint32_t* Vhi = Klo + 64 * FS;
    uint32_t* Vlo = Vhi + 64 * FS;
    __nv_bfloat16* Vhi_h = reinterpret_cast<__nv_bfloat16*>(Vhi);
    __nv_bfloat16* Vlo_h = reinterpret_cast<__nv_bfloat16*>(Vlo);

    const int tid  = threadIdx.x;
    const int lane = tid & 31;
    const int wid  = tid >> 5;
    const int lr   = lane >> 2;
    const int lc   = lane & 3;

    const int qt = (T_ / 64 - 1) - blockIdx.x;   // largest tiles first
    const int h  = blockIdx.y;
    const int b  = blockIdx.z;
    const int q0 = qt * 64;
    const size_t rowstride = 3 * DIM_;

    const int lrow  = tid >> 1;          // 0..63
    const int lhalf = (tid & 1) * 32;    // 0 or 32

    // ---- load Q once (scaled by 1/8), split hi/lo ----
    {
        const float* src = g_qkv + (size_t)(b * T_ + q0 + lrow) * rowstride
                           + h * HD_ + lhalf;
#pragma unroll
        for (int v = 0; v < 8; v++) {
            float4 f4 = *reinterpret_cast<const float4*>(src + v * 4);
            f4.x *= 0.125f; f4.y *= 0.125f; f4.z *= 0.125f; f4.w *= 0.125f;
            const int pi = (lhalf >> 1) + v * 2;
            Qhi[lrow * FS + pi + 0] = pack_hi2(f4.x, f4.y);
            Qhi[lrow * FS + pi + 1] = pack_hi2(f4.z, f4.w);
            Qlo[lrow * FS + pi + 0] = pack_lo2(f4.x, f4.y);
            Qlo[lrow * FS + pi + 1] = pack_lo2(f4.z, f4.w);
        }
    }

    float O[8][4];
#pragma unroll
    for (int nt = 0; nt < 8; nt++)
#pragma unroll
        for (int j = 0; j < 4; j++) O[nt][j] = 0.f;
    float m0 = -INFINITY, m1 = -INFINITY, l0 = 0.f, l1 = 0.f;

    for (int kt = 0; kt <= qt; kt++) {
        __syncthreads();
        // ---- load K tile (split) and V tile (transposed, split) ----
        {
            const float* ksrc = g_qkv + (size_t)(b * T_ + kt * 64 + lrow) * rowstride
                                + DIM_ + h * HD_ + lhalf;
            const float* vsrc = ksrc + DIM_;
#pragma unroll
            for (int v = 0; v < 8; v++) {
                float4 f4 = *reinterpret_cast<const float4*>(ksrc + v * 4);
                const int pi = (lhalf >> 1) + v * 2;
                Khi[lrow * FS + pi + 0] = pack_hi2(f4.x, f4.y);
                Khi[lrow * FS + pi + 1] = pack_hi2(f4.z, f4.w);
                Klo[lrow * FS + pi + 0] = pack_lo2(f4.x, f4.y);
                Klo[lrow * FS + pi + 1] = pack_lo2(f4.z, f4.w);

                float4 v4 = *reinterpret_cast<const float4*>(vsrc + v * 4);
                float vf[4] = {v4.x, v4.y, v4.z, v4.w};
#pragma unroll
                for (int e = 0; e < 4; e++) {
                    const int d = lhalf + v * 4 + e;
                    __nv_bfloat16 hh = __float2bfloat16_rn(vf[e]);
                    __nv_bfloat16 ll = __float2bfloat16_rn(vf[e] - __bfloat162float(hh));
                    Vhi_h[d * (2 * FS) + lrow] = hh;
                    Vlo_h[d * (2 * FS) + lrow] = ll;
                }
            }
        }
        __syncthreads();

        // ---- S = Q @ K^T ----
        float sf[8][4];
#pragma unroll
        for (int nt = 0; nt < 8; nt++)
#pragma unroll
            for (int j = 0; j < 4; j++) sf[nt][j] = 0.f;

#pragma unroll
        for (int ks = 0; ks < 4; ks++) {
            const int arow = wid * 16 + lr;
            const int koff = ks * 8 + lc;
            uint32_t ahi[4], alo[4];
            ahi[0] = Qhi[arow * FS + koff];
            ahi[1] = Qhi[(arow + 8) * FS + koff];
            ahi[2] = Qhi[arow * FS + koff + 4];
            ahi[3] = Qhi[(arow + 8) * FS + koff + 4];
            alo[0] = Qlo[arow * FS + koff];
            alo[1] = Qlo[(arow + 8) * FS + koff];
            alo[2] = Qlo[arow * FS + koff + 4];
            alo[3] = Qlo[(arow + 8) * FS + koff + 4];
#pragma unroll
            for (int nt = 0; nt < 8; nt++) {
                const int n = nt * 8 + lr;
                uint32_t bh[2] = {Khi[n * FS + koff], Khi[n * FS + koff + 4]};
                uint32_t bl[2] = {Klo[n * FS + koff], Klo[n * FS + koff + 4]};
                mma_bf16(sf[nt], ahi, bh);
                mma_bf16(sf[nt], ahi, bl);
                mma_bf16(sf[nt], alo, bh);
            }
        }

        // ---- causal mask on diagonal tile ----
        if (kt == qt) {
            const int r0 = wid * 16 + lr;
#pragma unroll
            for (int nt = 0; nt < 8; nt++) {
                const int c0 = nt * 8 + 2 * lc;
                if (c0 > r0)      sf[nt][0] = -INFINITY;
                if (c0 + 1 > r0)  sf[nt][1] = -INFINITY;
                if (c0 > r0 + 8)  sf[nt][2] = -INFINITY;
                if (c0 + 1 > r0 + 8) sf[nt][3] = -INFINITY;
            }
        }

        // ---- online softmax (rows lr and lr+8) ----
        float ml0 = -INFINITY, ml1 = -INFINITY;
#pragma unroll
        for (int nt = 0; nt < 8; nt++) {
            ml0 = fmaxf(ml0, fmaxf(sf[nt][0], sf[nt][1]));
            ml1 = fmaxf(ml1, fmaxf(sf[nt][2], sf[nt][3]));
        }
        ml0 = fmaxf(ml0, __shfl_xor_sync(0xffffffffu, ml0, 1));
        ml0 = fmaxf(ml0, __shfl_xor_sync(0xffffffffu, ml0, 2));
        ml1 = fmaxf(ml1, __shfl_xor_sync(0xffffffffu, ml1, 1));
        ml1 = fmaxf(ml1, __shfl_xor_sync(0xffffffffu, ml1, 2));

        const float mn0 = fmaxf(m0, ml0);
        const float mn1 = fmaxf(m1, ml1);
        const float al0 = __expf(m0 - mn0);
        const float al1 = __expf(m1 - mn1);

        float rs0 = 0.f, rs1 = 0.f;
#pragma unroll
        for (int nt = 0; nt < 8; nt++) {
            sf[nt][0] = __expf(sf[nt][0] - mn0);
            sf[nt][1] = __expf(sf[nt][1] - mn0);
            sf[nt][2] = __expf(sf[nt][2] - mn1);
            sf[nt][3] = __expf(sf[nt][3] - mn1);
            rs0 += sf[nt][0] + sf[nt][1];
            rs1 += sf[nt][2] + sf[nt][3];
        }
        rs0 += __shfl_xor_sync(0xffffffffu, rs0, 1);
        rs0 += __shfl_xor_sync(0xffffffffu, rs0, 2);
        rs1 += __shfl_xor_sync(0xffffffffu, rs1, 1);
        rs1 += __shfl_xor_sync(0xffffffffu, rs1, 2);

        l0 = l0 * al0 + rs0;
        l1 = l1 * al1 + rs1;
        m0 = mn0; m1 = mn1;
#pragma unroll
        for (int nt = 0; nt < 8; nt++) {
            O[nt][0] *= al0; O[nt][1] *= al0;
            O[nt][2] *= al1; O[nt][3] *= al1;
        }

        // ---- O += P @ V (P from registers) ----
#pragma unroll
        for (int ks = 0; ks < 4; ks++) {
            uint32_t ahi[4], alo[4];
            ahi[0] = pack_hi2(sf[2 * ks][0],     sf[2 * ks][1]);
            ahi[1] = pack_hi2(sf[2 * ks][2],     sf[2 * ks][3]);
            ahi[2] = pack_hi2(sf[2 * ks + 1][0], sf[2 * ks + 1][1]);
            ahi[3] = pack_hi2(sf[2 * ks + 1][2], sf[2 * ks + 1][3]);
            alo[0] = pack_lo2(sf[2 * ks][0],     sf[2 * ks][1]);
            alo[1] = pack_lo2(sf[2 * ks][2],     sf[2 * ks][3]);
            alo[2] = pack_lo2(sf[2 * ks + 1][0], sf[2 * ks + 1][1]);
            alo[3] = pack_lo2(sf[2 * ks + 1][2], sf[2 * ks + 1][3]);
            const int koff = ks * 8 + lc;
#pragma unroll
            for (int nt = 0; nt < 8; nt++) {
                const int n = nt * 8 + lr;
                uint32_t bh[2] = {Vhi[n * FS + koff], Vhi[n * FS + koff + 4]};
                uint32_t bl[2] = {Vlo[n * FS + koff], Vlo[n * FS + koff + 4]};
                mma_bf16(O[nt], ahi, bh);
                mma_bf16(O[nt], ahi, bl);
                mma_bf16(O[nt], alo, bh);
            }
        }
    }

    // ---- normalize + write ----
    const float inv0 = 1.0f / l0;
    const float inv1 = 1.0f / l1;
    const int r0 = q0 + wid * 16 + lr;
#pragma unroll
    for (int nt = 0; nt < 8; nt++) {
        const int col = h * HD_ + nt * 8 + 2 * lc;
        float2 v0 = make_float2(O[nt][0] * inv0, O[nt][1] * inv0);
        float2 v1 = make_float2(O[nt][2] * inv1, O[nt][3] * inv1);
        *reinterpret_cast<float2*>(&y[(size_t)(b * T_ + r0) * DIM_ + col]) = v0;
        *reinterpret_cast<float2*>(&y[(size_t)(b * T_ + r0 + 8) * DIM_ + col]) = v1;
    }
}

// ---------------------------------------------------------------------------
// Launch
// ---------------------------------------------------------------------------
extern "C" void kernel_launch(void* const* d_in, const int* in_sizes, int n_in,
                              void* d_out, int out_size) {
    const float* x      = (const float*)d_in[0];
    const float* sin_t  = (const float*)d_in[1];
    const float* cos_t  = (const float*)d_in[2];
    const float* W_qkv  = (const float*)d_in[3];
    const float* W_proj = (const float*)d_in[4];
    float* out = (float*)d_out;

    float* qkv_ptr = nullptr;
    float* y_ptr = nullptr;
    cudaGetSymbolAddress((void**)&qkv_ptr, g_qkv);
    cudaGetSymbolAddress((void**)&y_ptr, g_y);

    const int M = B_ * T_;

    // 1) QKV GEMM
    {
        dim3 grid((3 * DIM_) / BN, M / BM);
        gemm_bf16x3<<<grid, 256>>>(x, W_qkv, qkv_ptr, M, 3 * DIM_, DIM_);
    }

    // 2) RoPE
    {
        int total = B_ * T_ * NH_ * (HD_ / 2);
        rope_kernel<<<(total + 255) / 256, 256>>>(sin_t, cos_t);
    }

    // 3) Flash attention (tensor core)
    {
        cudaFuncSetAttribute(flash_mma, cudaFuncAttributeMaxDynamicSharedMemorySize,
                             FA_SMEM_BYTES);
        dim3 grid(T_ / 64, NH_, B_);
        flash_mma<<<grid, 128, FA_SMEM_BYTES>>>(y_ptr);
    }

    // 4) Output projection
    {
        dim3 grid(DIM_ / BN, M / BM);
        gemm_bf16x3<<<grid, 256>>>(y_ptr, W_proj, out, M, DIM_, DIM_);
    }
}

// round 4
// speedup vs baseline: 2.5044x; 1.6377x over previous
#include <cuda_runtime.h>
#include <cuda_bf16.h>
#include <math.h>
#include <stdint.h>

#define B_   2
#define T_   2048
#define DIM_ 1024
#define NH_  16
#define HD_  64

// fp32 scratch
__device__ float g_qkv[(size_t)B_ * T_ * 3 * DIM_];
__device__ float g_y  [(size_t)B_ * T_ * DIM_];

// packed bf16-pair scratch (hi/lo split)
__device__ uint32_t g_ahi[(size_t)4096 * 512];        // A operand (x, then y)
__device__ uint32_t g_alo[(size_t)4096 * 512];
__device__ uint32_t g_wthi[(size_t)3072 * 512];       // W transposed [N][K/2]
__device__ uint32_t g_wtlo[(size_t)3072 * 512];
__device__ uint32_t g_qhi[(size_t)B_ * NH_ * T_ * 32];
__device__ uint32_t g_qlo[(size_t)B_ * NH_ * T_ * 32];
__device__ uint32_t g_khi[(size_t)B_ * NH_ * T_ * 32];
__device__ uint32_t g_klo[(size_t)B_ * NH_ * T_ * 32];
__device__ uint32_t g_vthi[(size_t)B_ * NH_ * HD_ * (T_ / 2)];
__device__ uint32_t g_vtlo[(size_t)B_ * NH_ * HD_ * (T_ / 2)];

__device__ __forceinline__ void mma_bf16(float c[4], const uint32_t a[4],
                                         const uint32_t b[2]) {
    asm volatile(
        "mma.sync.aligned.m16n8k16.row.col.f32.bf16.bf16.f32 "
        "{%0,%1,%2,%3}, {%4,%5,%6,%7}, {%8,%9}, {%0,%1,%2,%3};\n"
        : "+f"(c[0]), "+f"(c[1]), "+f"(c[2]), "+f"(c[3])
        : "r"(a[0]), "r"(a[1]), "r"(a[2]), "r"(a[3]), "r"(b[0]), "r"(b[1]));
}

__device__ __forceinline__ uint32_t pack_hi2(float x, float y) {
    __nv_bfloat162 p = {__float2bfloat16_rn(x), __float2bfloat16_rn(y)};
    return *reinterpret_cast<uint32_t*>(&p);
}
__device__ __forceinline__ uint32_t pack_lo2(float x, float y) {
    float xh = __bfloat162float(__float2bfloat16_rn(x));
    float yh = __bfloat162float(__float2bfloat16_rn(y));
    __nv_bfloat162 p = {__float2bfloat16_rn(x - xh), __float2bfloat16_rn(y - yh)};
    return *reinterpret_cast<uint32_t*>(&p);
}

// ===========================================================================
// conv_rows: fp32 [M][K] -> hi/lo bf16-pair [M][K/2]
// ===========================================================================
__global__ __launch_bounds__(256) void conv_rows(const float* __restrict__ src,
                                                 uint32_t* __restrict__ hi,
                                                 uint32_t* __restrict__ lo,
                                                 int npairs) {
    const int i = blockIdx.x * blockDim.x + threadIdx.x;
    if (i >= npairs) return;
    float2 f = *reinterpret_cast<const float2*>(src + (size_t)i * 2);
    hi[i] = pack_hi2(f.x, f.y);
    lo[i] = pack_lo2(f.x, f.y);
}

// ===========================================================================
// conv_tr: fp32 W[K][N] -> transposed hi/lo pairs [N][K/2]
// ===========================================================================
__global__ __launch_bounds__(256) void conv_tr(const float* __restrict__ src,
                                               uint32_t* __restrict__ hi,
                                               uint32_t* __restrict__ lo,
                                               int K, int N) {
    __shared__ float vs[32][33];
    const int tid = threadIdx.x;
    const int n0 = blockIdx.x * 32;
    const int k0 = blockIdx.y * 32;
    const int Kp = K >> 1;
#pragma unroll
    for (int e = 0; e < 4; e++) {
        const int idx = tid + 256 * e;
        const int kl = idx >> 5, nl = idx & 31;
        vs[kl][nl] = src[(size_t)(k0 + kl) * N + n0 + nl];
    }
    __syncthreads();
#pragma unroll
    for (int e = 0; e < 2; e++) {
        const int idx = tid + 256 * e;
        const int nl = idx >> 4, p = idx & 15;
        float f0 = vs[2 * p][nl], f1 = vs[2 * p + 1][nl];
        const size_t o = (size_t)(n0 + nl) * Kp + (k0 >> 1) + p;
        hi[o] = pack_hi2(f0, f1);
        lo[o] = pack_lo2(f0, f1);
    }
}

// ===========================================================================
// gemm_pre: C[M,N] = A @ B with pre-split operands.
// Ahi/Alo: [M][Kp], Bthi/Btlo: [N][Kp].  Tile 128x64, BK=32 (16 pairs).
// ===========================================================================
#define BM 128
#define BN 64
#define SA_STRIDE 20
#define SB_STRIDE 20

__global__ __launch_bounds__(256) void gemm_pre(const uint32_t* __restrict__ Ahi,
                                                const uint32_t* __restrict__ Alo,
                                                const uint32_t* __restrict__ Bthi,
                                                const uint32_t* __restrict__ Btlo,
                                                float* __restrict__ C,
                                                int M, int N, int Kp) {
    __shared__ uint32_t sAhi[BM * SA_STRIDE];
    __shared__ uint32_t sAlo[BM * SA_STRIDE];
    __shared__ uint32_t sBhi[BN * SB_STRIDE];
    __shared__ uint32_t sBlo[BN * SB_STRIDE];

    const int tid  = threadIdx.x;
    const int lane = tid & 31;
    const int wid  = tid >> 5;
    const int wm   = wid & 3;
    const int wn   = wid >> 2;
    const int lr   = lane >> 2;
    const int lc   = lane & 3;

    const int m0 = blockIdx.y * BM;
    const int n0 = blockIdx.x * BN;

    float acc[2][4][4];
#pragma unroll
    for (int mt = 0; mt < 2; mt++)
#pragma unroll
        for (int nt = 0; nt < 4; nt++)
#pragma unroll
            for (int j = 0; j < 4; j++) acc[mt][nt][j] = 0.f;

    for (int k0p = 0; k0p < Kp; k0p += 16) {
        // A tile: 128 rows x 16 pairs = 1024 uint2
#pragma unroll
        for (int j = 0; j < 4; j++) {
            const int c = tid + 256 * j;
            const int row = c >> 3, cc = c & 7;
            uint2 vh = *reinterpret_cast<const uint2*>(
                &Ahi[(size_t)(m0 + row) * Kp + k0p + cc * 2]);
            uint2 vl = *reinterpret_cast<const uint2*>(
                &Alo[(size_t)(m0 + row) * Kp + k0p + cc * 2]);
            *reinterpret_cast<uint2*>(&sAhi[row * SA_STRIDE + cc * 2]) = vh;
            *reinterpret_cast<uint2*>(&sAlo[row * SA_STRIDE + cc * 2]) = vl;
        }
        // B tile: 64 rows x 16 pairs = 512 uint2
#pragma unroll
        for (int j = 0; j < 2; j++) {
            const int c = tid + 256 * j;
            const int row = c >> 3, cc = c & 7;
            uint2 vh = *reinterpret_cast<const uint2*>(
                &Bthi[(size_t)(n0 + row) * Kp + k0p + cc * 2]);
            uint2 vl = *reinterpret_cast<const uint2*>(
                &Btlo[(size_t)(n0 + row) * Kp + k0p + cc * 2]);
            *reinterpret_cast<uint2*>(&sBhi[row * SB_STRIDE + cc * 2]) = vh;
            *reinterpret_cast<uint2*>(&sBlo[row * SB_STRIDE + cc * 2]) = vl;
        }
        __syncthreads();

#pragma unroll
        for (int ks = 0; ks < 2; ks++) {
            uint32_t ahi[2][4], alo[2][4];
#pragma unroll
            for (int mt = 0; mt < 2; mt++) {
                const int r = wm * 32 + mt * 16 + lr;
                const int base = ks * 8 + lc;
                ahi[mt][0] = sAhi[r * SA_STRIDE + base];
                ahi[mt][1] = sAhi[(r + 8) * SA_STRIDE + base];
                ahi[mt][2] = sAhi[r * SA_STRIDE + base + 4];
                ahi[mt][3] = sAhi[(r + 8) * SA_STRIDE + base + 4];
                alo[mt][0] = sAlo[r * SA_STRIDE + base];
                alo[mt][1] = sAlo[(r + 8) * SA_STRIDE + base];
                alo[mt][2] = sAlo[r * SA_STRIDE + base + 4];
                alo[mt][3] = sAlo[(r + 8) * SA_STRIDE + base + 4];
            }
            uint32_t bhi[4][2], blo[4][2];
#pragma unroll
            for (int nt = 0; nt < 4; nt++) {
                const int n = wn * 32 + nt * 8 + lr;
                const int base = ks * 8 + lc;
                bhi[nt][0] = sBhi[n * SB_STRIDE + base];
                bhi[nt][1] = sBhi[n * SB_STRIDE + base + 4];
                blo[nt][0] = sBlo[n * SB_STRIDE + base];
                blo[nt][1] = sBlo[n * SB_STRIDE + base + 4];
            }
#pragma unroll
            for (int mt = 0; mt < 2; mt++)
#pragma unroll
                for (int nt = 0; nt < 4; nt++) {
                    mma_bf16(acc[mt][nt], ahi[mt], bhi[nt]);
                    mma_bf16(acc[mt][nt], ahi[mt], blo[nt]);
                    mma_bf16(acc[mt][nt], alo[mt], bhi[nt]);
                }
        }
        __syncthreads();
    }

#pragma unroll
    for (int mt = 0; mt < 2; mt++) {
#pragma unroll
        for (int nt = 0; nt < 4; nt++) {
            const int row0 = m0 + wm * 32 + mt * 16 + lr;
            const int col  = n0 + wn * 32 + nt * 8 + lc * 2;
            float2 v0 = make_float2(acc[mt][nt][0], acc[mt][nt][1]);
            float2 v1 = make_float2(acc[mt][nt][2], acc[mt][nt][3]);
            *reinterpret_cast<float2*>(&C[(size_t)row0 * N + col]) = v0;
            *reinterpret_cast<float2*>(&C[(size_t)(row0 + 8) * N + col]) = v1;
        }
    }
}

// ===========================================================================
// rope_conv: RoPE q,k; scale q by 0.125; split -> [b,h,t,d] bf16 pairs
// ===========================================================================
__global__ __launch_bounds__(256) void rope_conv(const float* __restrict__ sin_t,
                                                 const float* __restrict__ cos_t) {
    const int idx = blockIdx.x * blockDim.x + threadIdx.x;
    const int total = B_ * T_ * NH_ * (HD_ / 2);
    if (idx >= total) return;
    const int i = idx & 31;
    const int h = (idx >> 5) & (NH_ - 1);
    const int bt = idx >> 9;
    const int t = bt & (T_ - 1);
    const int b = bt >> 11;

    const float s = sin_t[t * HD_ + 2 * i];
    const float c = cos_t[t * HD_ + 2 * i];

    const float* row = g_qkv + (size_t)bt * (3 * DIM_);
    const size_t o = ((size_t)(b * NH_ + h) * T_ + t) * 32 + i;

    float2 q = *reinterpret_cast<const float2*>(row + h * HD_ + 2 * i);
    float q0 = (q.x * c - q.y * s) * 0.125f;
    float q1 = (q.y * c + q.x * s) * 0.125f;
    g_qhi[o] = pack_hi2(q0, q1);
    g_qlo[o] = pack_lo2(q0, q1);

    float2 k = *reinterpret_cast<const float2*>(row + DIM_ + h * HD_ + 2 * i);
    float k0 = k.x * c - k.y * s;
    float k1 = k.y * c + k.x * s;
    g_khi[o] = pack_hi2(k0, k1);
    g_klo[o] = pack_lo2(k0, k1);
}

// ===========================================================================
// vtrans_conv: V fp32 [b,t, 2*DIM + h*64 + d] -> transposed split [b,h,d,t]
// ===========================================================================
__global__ __launch_bounds__(256) void vtrans_conv() {
    __shared__ float vs[64][65];
    const int tid = threadIdx.x;
    const int t0 = blockIdx.x * 64;
    const int h  = blockIdx.y;
    const int b  = blockIdx.z;

    const int r = tid >> 2;
    const int q = (tid & 3) * 16;
    const float* src = g_qkv + (size_t)(b * T_ + t0 + r) * (3 * DIM_) + 2 * DIM_ + h * HD_;
#pragma unroll
    for (int v = 0; v < 4; v++) {
        float4 f4 = *reinterpret_cast<const float4*>(src + q + v * 4);
        vs[r][q + v * 4 + 0] = f4.x;
        vs[r][q + v * 4 + 1] = f4.y;
        vs[r][q + v * 4 + 2] = f4.z;
        vs[r][q + v * 4 + 3] = f4.w;
    }
    __syncthreads();

    const int Tp = T_ / 2;
#pragma unroll
    for (int j = 0; j < 8; j++) {
        const int c = tid + 256 * j;
        const int d = c >> 5, p = c & 31;
        float f0 = vs[2 * p][d], f1 = vs[2 * p + 1][d];
        const size_t o = ((size_t)(b * NH_ + h) * HD_ + d) * Tp + (t0 >> 1) + p;
        g_vthi[o] = pack_hi2(f0, f1);
        g_vtlo[o] = pack_lo2(f0, f1);
    }
}

// ===========================================================================
// Flash attention, BQ=128, 8 warps, pre-split bf16 operands.
// ===========================================================================
#define FS 36
#define FA_SMEM_BYTES ((2 * 128 + 4 * 64) * FS * 4)   // 73,728

__global__ __launch_bounds__(256) void flash_mma(float* __restrict__ y) {
    extern __shared__ uint32_t sm[];
    uint32_t* Qhi = sm;                     // 128 x FS
    uint32_t* Qlo = Qhi + 128 * FS;
    uint32_t* Khi = Qlo + 128 * FS;         // 64 x FS
    uint32_t* Klo = Khi + 64 * FS;
    uint32_t* Vhi = Klo + 64 * FS;          // 64 x FS (transposed: row=d)
    uint32_t* Vlo = Vhi + 64 * FS;

    const int tid  = threadIdx.x;
    const int lane = tid & 31;
    const int wid  = tid >> 5;
    const int lr   = lane >> 2;
    const int lc   = lane & 3;

    const int qt = (T_ / 128 - 1) - blockIdx.x;
    const int h  = blockIdx.y;
    const int b  = blockIdx.z;
    const int q0 = qt * 128;
    const size_t hb = (size_t)(b * NH_ + h);
    const int Tp = T_ / 2;

    // ---- load Q tile (128 rows) ----
#pragma unroll
    for (int j = 0; j < 8; j++) {
        const int c = tid + 256 * j;
        const int row = c >> 4, cc = c & 15;
        uint2 vh = *reinterpret_cast<const uint2*>(
            &g_qhi[(hb * T_ + q0 + row) * 32 + cc * 2]);
        uint2 vl = *reinterpret_cast<const uint2*>(
            &g_qlo[(hb * T_ + q0 + row) * 32 + cc * 2]);
        *reinterpret_cast<uint2*>(&Qhi[row * FS + cc * 2]) = vh;
        *reinterpret_cast<uint2*>(&Qlo[row * FS + cc * 2]) = vl;
    }

    float O[8][4];
#pragma unroll
    for (int nt = 0; nt < 8; nt++)
#pragma unroll
        for (int j = 0; j < 4; j++) O[nt][j] = 0.f;
    float m0 = -INFINITY, m1 = -INFINITY, l0 = 0.f, l1 = 0.f;

    const int kt_max = 2 * qt + 1;
    for (int kt = 0; kt <= kt_max; kt++) {
        __syncthreads();
        // ---- copy K tile and V^T tile ----
#pragma unroll
        for (int j = 0; j < 4; j++) {
            const int c = tid + 256 * j;
            const int row = c >> 4, cc = c & 15;
            uint2 kh = *reinterpret_cast<const uint2*>(
                &g_khi[(hb * T_ + kt * 64 + row) * 32 + cc * 2]);
            uint2 kl = *reinterpret_cast<const uint2*>(
                &g_klo[(hb * T_ + kt * 64 + row) * 32 + cc * 2]);
            *reinterpret_cast<uint2*>(&Khi[row * FS + cc * 2]) = kh;
            *reinterpret_cast<uint2*>(&Klo[row * FS + cc * 2]) = kl;
            uint2 vh = *reinterpret_cast<const uint2*>(
                &g_vthi[(hb * HD_ + row) * Tp + kt * 32 + cc * 2]);
            uint2 vl = *reinterpret_cast<const uint2*>(
                &g_vtlo[(hb * HD_ + row) * Tp + kt * 32 + cc * 2]);
            *reinterpret_cast<uint2*>(&Vhi[row * FS + cc * 2]) = vh;
            *reinterpret_cast<uint2*>(&Vlo[row * FS + cc * 2]) = vl;
        }
        __syncthreads();

        // warp fully above the diagonal for this key tile? skip.
        const int rel = kt * 64 - q0;            // key offset relative to q0
        if (rel > wid * 16 + 15) continue;

        // ---- S = Q @ K^T ----
        float sf[8][4];
#pragma unroll
        for (int nt = 0; nt < 8; nt++)
#pragma unroll
            for (int j = 0; j < 4; j++) sf[nt][j] = 0.f;

#pragma unroll
        for (int ks = 0; ks < 4; ks++) {
            const int arow = wid * 16 + lr;
            const int koff = ks * 8 + lc;
            uint32_t ahi[4], alo[4];
            ahi[0] = Qhi[arow * FS + koff];
            ahi[1] = Qhi[(arow + 8) * FS + koff];
            ahi[2] = Qhi[arow * FS + koff + 4];
            ahi[3] = Qhi[(arow + 8) * FS + koff + 4];
            alo[0] = Qlo[arow * FS + koff];
            alo[1] = Qlo[(arow + 8) * FS + koff];
            alo[2] = Qlo[arow * FS + koff + 4];
            alo[3] = Qlo[(arow + 8) * FS + koff + 4];
#pragma unroll
            for (int nt = 0; nt < 8; nt++) {
                const int n = nt * 8 + lr;
                uint32_t bh[2] = {Khi[n * FS + koff], Khi[n * FS + koff + 4]};
                uint32_t bl[2] = {Klo[n * FS + koff], Klo[n * FS + koff + 4]};
                mma_bf16(sf[nt], ahi, bh);
                mma_bf16(sf[nt], ahi, bl);
                mma_bf16(sf[nt], alo, bh);
            }
        }

        // ---- causal mask (diagonal-overlapping tiles only) ----
        if (rel + 63 > wid * 16) {
            const int r0 = wid * 16 + lr;
#pragma unroll
            for (int nt = 0; nt < 8; nt++) {
                const int c0 = rel + nt * 8 + 2 * lc;
                if (c0 > r0)         sf[nt][0] = -INFINITY;
                if (c0 + 1 > r0)     sf[nt][1] = -INFINITY;
                if (c0 > r0 + 8)     sf[nt][2] = -INFINITY;
                if (c0 + 1 > r0 + 8) sf[nt][3] = -INFINITY;
            }
        }

        // ---- online softmax ----
        float ml0 = -INFINITY, ml1 = -INFINITY;
#pragma unroll
        for (int nt = 0; nt < 8; nt++) {
            ml0 = fmaxf(ml0, fmaxf(sf[nt][0], sf[nt][1]));
            ml1 = fmaxf(ml1, fmaxf(sf[nt][2], sf[nt][3]));
        }
        ml0 = fmaxf(ml0, __shfl_xor_sync(0xffffffffu, ml0, 1));
        ml0 = fmaxf(ml0, __shfl_xor_sync(0xffffffffu, ml0, 2));
        ml1 = fmaxf(ml1, __shfl_xor_sync(0xffffffffu, ml1, 1));
        ml1 = fmaxf(ml1, __shfl_xor_sync(0xffffffffu, ml1, 2));

        const float mn0 = fmaxf(m0, ml0);
        const float mn1 = fmaxf(m1, ml1);
        const float al0 = __expf(m0 - mn0);
        const float al1 = __expf(m1 - mn1);

        float rs0 = 0.f, rs1 = 0.f;
#pragma unroll
        for (int nt = 0; nt < 8; nt++) {
            sf[nt][0] = __expf(sf[nt][0] - mn0);
            sf[nt][1] = __expf(sf[nt][1] - mn0);
            sf[nt][2] = __expf(sf[nt][2] - mn1);
            sf[nt][3] = __expf(sf[nt][3] - mn1);
            rs0 += sf[nt][0] + sf[nt][1];
            rs1 += sf[nt][2] + sf[nt][3];
        }
        rs0 += __shfl_xor_sync(0xffffffffu, rs0, 1);
        rs0 += __shfl_xor_sync(0xffffffffu, rs0, 2);
        rs1 += __shfl_xor_sync(0xffffffffu, rs1, 1);
        rs1 += __shfl_xor_sync(0xffffffffu, rs1, 2);

        l0 = l0 * al0 + rs0;
        l1 = l1 * al1 + rs1;
        m0 = mn0; m1 = mn1;
#pragma unroll
        for (int nt = 0; nt < 8; nt++) {
            O[nt][0] *= al0; O[nt][1] *= al0;
            O[nt][2] *= al1; O[nt][3] *= al1;
        }

        // ---- O += P @ V ----
#pragma unroll
        for (int ks = 0; ks < 4; ks++) {
            uint32_t ahi[4], alo[4];
            ahi[0] = pack_hi2(sf[2 * ks][0],     sf[2 * ks][1]);
            ahi[1] = pack_hi2(sf[2 * ks][2],     sf[2 * ks][3]);
            ahi[2] = pack_hi2(sf[2 * ks + 1][0], sf[2 * ks + 1][1]);
            ahi[3] = pack_hi2(sf[2 * ks + 1][2], sf[2 * ks + 1][3]);
            alo[0] = pack_lo2(sf[2 * ks][0],     sf[2 * ks][1]);
            alo[1] = pack_lo2(sf[2 * ks][2],     sf[2 * ks][3]);
            alo[2] = pack_lo2(sf[2 * ks + 1][0], sf[2 * ks + 1][1]);
            alo[3] = pack_lo2(sf[2 * ks + 1][2], sf[2 * ks + 1][3]);
            const int koff = ks * 8 + lc;
#pragma unroll
            for (int nt = 0; nt < 8; nt++) {
                const int n = nt * 8 + lr;
                uint32_t bh[2] = {Vhi[n * FS + koff], Vhi[n * FS + koff + 4]};
                uint32_t bl[2] = {Vlo[n * FS + koff], Vlo[n * FS + koff + 4]};
                mma_bf16(O[nt], ahi, bh);
                mma_bf16(O[nt], ahi, bl);
                mma_bf16(O[nt], alo, bh);
            }
        }
    }

    // ---- normalize + write ----
    const float inv0 = 1.0f / l0;
    const float inv1 = 1.0f / l1;
    const int r0 = q0 + wid * 16 + lr;
#pragma unroll
    for (int nt = 0; nt < 8; nt++) {
        const int col = h * HD_ + nt * 8 + 2 * lc;
        float2 v0 = make_float2(O[nt][0] * inv0, O[nt][1] * inv0);
        float2 v1 = make_float2(O[nt][2] * inv1, O[nt][3] * inv1);
        *reinterpret_cast<float2*>(&y[(size_t)(b * T_ + r0) * DIM_ + col]) = v0;
        *reinterpret_cast<float2*>(&y[(size_t)(b * T_ + r0 + 8) * DIM_ + col]) = v1;
    }
}

// ---------------------------------------------------------------------------
// Launch
// ---------------------------------------------------------------------------
extern "C" void kernel_launch(void* const* d_in, const int* in_sizes, int n_in,
                              void* d_out, int out_size) {
    const float* x      = (const float*)d_in[0];
    const float* sin_t  = (const float*)d_in[1];
    const float* cos_t  = (const float*)d_in[2];
    const float* W_qkv  = (const float*)d_in[3];
    const float* W_proj = (const float*)d_in[4];
    float* out = (float*)d_out;

    float *qkv_ptr = nullptr, *y_ptr = nullptr;
    uint32_t *ahi, *alo, *wthi, *wtlo;
    cudaGetSymbolAddress((void**)&qkv_ptr, g_qkv);
    cudaGetSymbolAddress((void**)&y_ptr, g_y);
    cudaGetSymbolAddress((void**)&ahi, g_ahi);
    cudaGetSymbolAddress((void**)&alo, g_alo);
    cudaGetSymbolAddress((void**)&wthi, g_wthi);
    cudaGetSymbolAddress((void**)&wtlo, g_wtlo);

    const int M = B_ * T_;           // 4096
    const int Kp = DIM_ / 2;         // 512

    // 1) split x; transpose+split W_qkv; QKV GEMM
    conv_rows<<<(M * Kp) / 256, 256>>>(x, ahi, alo, M * Kp);
    {
        dim3 g(3 * DIM_ / 32, DIM_ / 32);
        conv_tr<<<g, 256>>>(W_qkv, wthi, wtlo, DIM_, 3 * DIM_);
    }
    {
        dim3 g((3 * DIM_) / BN, M / BM);
        gemm_pre<<<g, 256>>>(ahi, alo, wthi, wtlo, qkv_ptr, M, 3 * DIM_, Kp);
    }

    // 2) RoPE + split q/k; transpose + split v
    {
        int total = B_ * T_ * NH_ * (HD_ / 2);
        rope_conv<<<(total + 255) / 256, 256>>>(sin_t, cos_t);
    }
    {
        dim3 g(T_ / 64, NH_, B_);
        vtrans_conv<<<g, 256>>>();
    }

    // 3) Flash attention
    {
        cudaFuncSetAttribute(flash_mma, cudaFuncAttributeMaxDynamicSharedMemorySize,
                             FA_SMEM_BYTES);
        dim3 g(T_ / 128, NH_, B_);
        flash_mma<<<g, 256, FA_SMEM_BYTES>>>(y_ptr);
    }

    // 4) split y; transpose+split W_proj; output projection
    conv_rows<<<(M * Kp) / 256, 256>>>(y_ptr, ahi, alo, M * Kp);
    {
        dim3 g(DIM_ / 32, DIM_ / 32);
        conv_tr<<<g, 256>>>(W_proj, wthi, wtlo, DIM_, DIM_);
    }
    {
        dim3 g(DIM_ / BN, M / BM);
        gemm_pre<<<g, 256>>>(ahi, alo, wthi, wtlo, out, M, DIM_, Kp);
    }
}

// round 5
// speedup vs baseline: 2.8016x; 1.1187x over previous
#include <cuda_runtime.h>
#include <cuda_bf16.h>
#include <math.h>
#include <stdint.h>

#define B_   2
#define T_   2048
#define DIM_ 1024
#define NH_  16
#define HD_  64

// fp32 scratch
__device__ float g_qkv[(size_t)B_ * T_ * 3 * DIM_];

// packed bf16-pair scratch (hi/lo split)
__device__ uint32_t g_ahi[(size_t)4096 * 512];        // A operand (x, then attn-out)
__device__ uint32_t g_alo[(size_t)4096 * 512];
__device__ uint32_t g_wthi[(size_t)3072 * 512];       // W transposed [N][K/2]
__device__ uint32_t g_wtlo[(size_t)3072 * 512];
__device__ uint32_t g_qhi[(size_t)B_ * NH_ * T_ * 32];
__device__ uint32_t g_qlo[(size_t)B_ * NH_ * T_ * 32];
__device__ uint32_t g_khi[(size_t)B_ * NH_ * T_ * 32];
__device__ uint32_t g_klo[(size_t)B_ * NH_ * T_ * 32];
__device__ uint32_t g_vthi[(size_t)B_ * NH_ * HD_ * (T_ / 2)];
__device__ uint32_t g_vtlo[(size_t)B_ * NH_ * HD_ * (T_ / 2)];

__device__ __forceinline__ void mma_bf16(float c[4], const uint32_t a[4],
                                         const uint32_t b[2]) {
    asm volatile(
        "mma.sync.aligned.m16n8k16.row.col.f32.bf16.bf16.f32 "
        "{%0,%1,%2,%3}, {%4,%5,%6,%7}, {%8,%9}, {%0,%1,%2,%3};\n"
        : "+f"(c[0]), "+f"(c[1]), "+f"(c[2]), "+f"(c[3])
        : "r"(a[0]), "r"(a[1]), "r"(a[2]), "r"(a[3]), "r"(b[0]), "r"(b[1]));
}

__device__ __forceinline__ uint32_t pack_hi2(float x, float y) {
    __nv_bfloat162 p = {__float2bfloat16_rn(x), __float2bfloat16_rn(y)};
    return *reinterpret_cast<uint32_t*>(&p);
}
__device__ __forceinline__ uint32_t pack_lo2(float x, float y) {
    float xh = __bfloat162float(__float2bfloat16_rn(x));
    float yh = __bfloat162float(__float2bfloat16_rn(y));
    __nv_bfloat162 p = {__float2bfloat16_rn(x - xh), __float2bfloat16_rn(y - yh)};
    return *reinterpret_cast<uint32_t*>(&p);
}

__device__ __forceinline__ void cp16(uint32_t dst_smem, const void* src) {
    asm volatile("cp.async.cg.shared.global [%0], [%1], 16;\n"
                 :: "r"(dst_smem), "l"(src));
}
#define CP_COMMIT() asm volatile("cp.async.commit_group;\n" ::: "memory")
#define CP_WAIT_1() asm volatile("cp.async.wait_group 1;\n" ::: "memory")
#define CP_WAIT_0() asm volatile("cp.async.wait_group 0;\n" ::: "memory")

// ===========================================================================
// conv_rows: fp32 [M][K] -> hi/lo bf16-pair [M][K/2]
// ===========================================================================
__global__ __launch_bounds__(256) void conv_rows(const float* __restrict__ src,
                                                 uint32_t* __restrict__ hi,
                                                 uint32_t* __restrict__ lo,
                                                 int npairs) {
    const int i = blockIdx.x * blockDim.x + threadIdx.x;
    if (i >= npairs) return;
    float2 f = *reinterpret_cast<const float2*>(src + (size_t)i * 2);
    hi[i] = pack_hi2(f.x, f.y);
    lo[i] = pack_lo2(f.x, f.y);
}

// ===========================================================================
// conv_tr: fp32 W[K][N] -> transposed hi/lo pairs [N][K/2]
// ===========================================================================
__global__ __launch_bounds__(256) void conv_tr(const float* __restrict__ src,
                                               uint32_t* __restrict__ hi,
                                               uint32_t* __restrict__ lo,
                                               int K, int N) {
    __shared__ float vs[32][33];
    const int tid = threadIdx.x;
    const int n0 = blockIdx.x * 32;
    const int k0 = blockIdx.y * 32;
    const int Kp = K >> 1;
#pragma unroll
    for (int e = 0; e < 4; e++) {
        const int idx = tid + 256 * e;
        const int kl = idx >> 5, nl = idx & 31;
        vs[kl][nl] = src[(size_t)(k0 + kl) * N + n0 + nl];
    }
    __syncthreads();
#pragma unroll
    for (int e = 0; e < 2; e++) {
        const int idx = tid + 256 * e;
        const int nl = idx >> 4, p = idx & 15;
        float f0 = vs[2 * p][nl], f1 = vs[2 * p + 1][nl];
        const size_t o = (size_t)(n0 + nl) * Kp + (k0 >> 1) + p;
        hi[o] = pack_hi2(f0, f1);
        lo[o] = pack_lo2(f0, f1);
    }
}

// ===========================================================================
// gemm_pre: C = A @ B, pre-split operands, cp.async double-buffered.
// Tile 128x64, BK=32 (16 pairs). Dynamic smem: 2 stages x 7680 uint32.
// Stage layout (uint32): Ahi[0..2560) Alo[2560..5120) Bhi[5120..6400) Blo[6400..7680)
// ===========================================================================
#define BM 128
#define BN 64
#define SA_STRIDE 20
#define SB_STRIDE 20
#define G_STAGE 7680
#define GEMM_SMEM_BYTES (2 * G_STAGE * 4)

__global__ __launch_bounds__(256) void gemm_pre(const uint32_t* __restrict__ Ahi,
                                                const uint32_t* __restrict__ Alo,
                                                const uint32_t* __restrict__ Bthi,
                                                const uint32_t* __restrict__ Btlo,
                                                float* __restrict__ C,
                                                int M, int N, int Kp) {
    extern __shared__ uint32_t sm[];
    const uint32_t sm_u32 = (uint32_t)__cvta_generic_to_shared(sm);

    const int tid  = threadIdx.x;
    const int lane = tid & 31;
    const int wid  = tid >> 5;
    const int wm   = wid & 3;
    const int wn   = wid >> 2;
    const int lr   = lane >> 2;
    const int lc   = lane & 3;

    const int m0 = blockIdx.y * BM;
    const int n0 = blockIdx.x * BN;

    float acc[2][4][4];
#pragma unroll
    for (int mt = 0; mt < 2; mt++)
#pragma unroll
        for (int nt = 0; nt < 4; nt++)
#pragma unroll
            for (int j = 0; j < 4; j++) acc[mt][nt][j] = 0.f;

    const int Kt = Kp / 16;   // number of k-tiles

    // prefetch lambda: stage s, k-tile index kt
    auto prefetch = [&](int kt, int s) {
        const int k0p = kt * 16;
        const uint32_t base = sm_u32 + s * G_STAGE * 4;
#pragma unroll
        for (int j = 0; j < 2; j++) {
            const int idx = tid + 256 * j;
            const int row = idx >> 2, ch = idx & 3;
            cp16(base + (row * SA_STRIDE + ch * 4) * 4,
                 &Ahi[(size_t)(m0 + row) * Kp + k0p + ch * 4]);
            cp16(base + (2560 + row * SA_STRIDE + ch * 4) * 4,
                 &Alo[(size_t)(m0 + row) * Kp + k0p + ch * 4]);
        }
        {
            const int row = tid >> 2, ch = tid & 3;
            cp16(base + (5120 + row * SB_STRIDE + ch * 4) * 4,
                 &Bthi[(size_t)(n0 + row) * Kp + k0p + ch * 4]);
            cp16(base + (6400 + row * SB_STRIDE + ch * 4) * 4,
                 &Btlo[(size_t)(n0 + row) * Kp + k0p + ch * 4]);
        }
    };

    prefetch(0, 0);
    CP_COMMIT();

    for (int kt = 0; kt < Kt; kt++) {
        if (kt + 1 < Kt) {
            prefetch(kt + 1, (kt + 1) & 1);
            CP_COMMIT();
            CP_WAIT_1();
        } else {
            CP_WAIT_0();
        }
        __syncthreads();

        const uint32_t* sAhi = sm + (kt & 1) * G_STAGE;
        const uint32_t* sAlo = sAhi + 2560;
        const uint32_t* sBhi = sAhi + 5120;
        const uint32_t* sBlo = sAhi + 6400;

#pragma unroll
        for (int ks = 0; ks < 2; ks++) {
            uint32_t ahi[2][4], alo[2][4];
#pragma unroll
            for (int mt = 0; mt < 2; mt++) {
                const int r = wm * 32 + mt * 16 + lr;
                const int base = ks * 8 + lc;
                ahi[mt][0] = sAhi[r * SA_STRIDE + base];
                ahi[mt][1] = sAhi[(r + 8) * SA_STRIDE + base];
                ahi[mt][2] = sAhi[r * SA_STRIDE + base + 4];
                ahi[mt][3] = sAhi[(r + 8) * SA_STRIDE + base + 4];
                alo[mt][0] = sAlo[r * SA_STRIDE + base];
                alo[mt][1] = sAlo[(r + 8) * SA_STRIDE + base];
                alo[mt][2] = sAlo[r * SA_STRIDE + base + 4];
                alo[mt][3] = sAlo[(r + 8) * SA_STRIDE + base + 4];
            }
            uint32_t bhi[4][2], blo[4][2];
#pragma unroll
            for (int nt = 0; nt < 4; nt++) {
                const int n = wn * 32 + nt * 8 + lr;
                const int base = ks * 8 + lc;
                bhi[nt][0] = sBhi[n * SB_STRIDE + base];
                bhi[nt][1] = sBhi[n * SB_STRIDE + base + 4];
                blo[nt][0] = sBlo[n * SB_STRIDE + base];
                blo[nt][1] = sBlo[n * SB_STRIDE + base + 4];
            }
#pragma unroll
            for (int mt = 0; mt < 2; mt++)
#pragma unroll
                for (int nt = 0; nt < 4; nt++) {
                    mma_bf16(acc[mt][nt], ahi[mt], bhi[nt]);
                    mma_bf16(acc[mt][nt], ahi[mt], blo[nt]);
                    mma_bf16(acc[mt][nt], alo[mt], bhi[nt]);
                }
        }
        __syncthreads();
    }

#pragma unroll
    for (int mt = 0; mt < 2; mt++) {
#pragma unroll
        for (int nt = 0; nt < 4; nt++) {
            const int row0 = m0 + wm * 32 + mt * 16 + lr;
            const int col  = n0 + wn * 32 + nt * 8 + lc * 2;
            float2 v0 = make_float2(acc[mt][nt][0], acc[mt][nt][1]);
            float2 v1 = make_float2(acc[mt][nt][2], acc[mt][nt][3]);
            *reinterpret_cast<float2*>(&C[(size_t)row0 * N + col]) = v0;
            *reinterpret_cast<float2*>(&C[(size_t)(row0 + 8) * N + col]) = v1;
        }
    }
}

// ===========================================================================
// rope_conv: RoPE q,k; scale q by 0.125; split -> [b,h,t,d] bf16 pairs
// ===========================================================================
__global__ __launch_bounds__(256) void rope_conv(const float* __restrict__ sin_t,
                                                 const float* __restrict__ cos_t) {
    const int idx = blockIdx.x * blockDim.x + threadIdx.x;
    const int total = B_ * T_ * NH_ * (HD_ / 2);
    if (idx >= total) return;
    const int i = idx & 31;
    const int h = (idx >> 5) & (NH_ - 1);
    const int bt = idx >> 9;
    const int t = bt & (T_ - 1);
    const int b = bt >> 11;

    const float s = sin_t[t * HD_ + 2 * i];
    const float c = cos_t[t * HD_ + 2 * i];

    const float* row = g_qkv + (size_t)bt * (3 * DIM_);
    const size_t o = ((size_t)(b * NH_ + h) * T_ + t) * 32 + i;

    float2 q = *reinterpret_cast<const float2*>(row + h * HD_ + 2 * i);
    float q0 = (q.x * c - q.y * s) * 0.125f;
    float q1 = (q.y * c + q.x * s) * 0.125f;
    g_qhi[o] = pack_hi2(q0, q1);
    g_qlo[o] = pack_lo2(q0, q1);

    float2 k = *reinterpret_cast<const float2*>(row + DIM_ + h * HD_ + 2 * i);
    float k0 = k.x * c - k.y * s;
    float k1 = k.y * c + k.x * s;
    g_khi[o] = pack_hi2(k0, k1);
    g_klo[o] = pack_lo2(k0, k1);
}

// ===========================================================================
// vtrans_conv: V fp32 -> transposed split [b,h,d,t]
// ===========================================================================
__global__ __launch_bounds__(256) void vtrans_conv() {
    __shared__ float vs[64][65];
    const int tid = threadIdx.x;
    const int t0 = blockIdx.x * 64;
    const int h  = blockIdx.y;
    const int b  = blockIdx.z;

    const int r = tid >> 2;
    const int q = (tid & 3) * 16;
    const float* src = g_qkv + (size_t)(b * T_ + t0 + r) * (3 * DIM_) + 2 * DIM_ + h * HD_;
#pragma unroll
    for (int v = 0; v < 4; v++) {
        float4 f4 = *reinterpret_cast<const float4*>(src + q + v * 4);
        vs[r][q + v * 4 + 0] = f4.x;
        vs[r][q + v * 4 + 1] = f4.y;
        vs[r][q + v * 4 + 2] = f4.z;
        vs[r][q + v * 4 + 3] = f4.w;
    }
    __syncthreads();

    const int Tp = T_ / 2;
#pragma unroll
    for (int j = 0; j < 8; j++) {
        const int c = tid + 256 * j;
        const int d = c >> 5, p = c & 31;
        float f0 = vs[2 * p][d], f1 = vs[2 * p + 1][d];
        const size_t o = ((size_t)(b * NH_ + h) * HD_ + d) * Tp + (t0 >> 1) + p;
        g_vthi[o] = pack_hi2(f0, f1);
        g_vtlo[o] = pack_lo2(f0, f1);
    }
}

// ===========================================================================
// Flash attention, BQ=128, 8 warps, cp.async double-buffered K/V.
// smem (uint32): Q hi/lo [0..9216); KV stages at 9216 + s*9216:
//   Khi[0..2304) Klo[2304..4608) Vhi[4608..6912) Vlo[6912..9216)
// Output written directly in split bf16-pair format to g_ahi/g_alo.
// ===========================================================================
#define FS 36
#define F_STAGE 9216
#define FA_SMEM_BYTES ((9216 + 2 * F_STAGE) * 4)   // 110,592

__global__ __launch_bounds__(256) void flash_mma(uint32_t* __restrict__ yhi,
                                                 uint32_t* __restrict__ ylo) {
    extern __shared__ uint32_t sm[];
    const uint32_t sm_u32 = (uint32_t)__cvta_generic_to_shared(sm);
    uint32_t* Qhi = sm;
    uint32_t* Qlo = Qhi + 128 * FS;

    const int tid  = threadIdx.x;
    const int lane = tid & 31;
    const int wid  = tid >> 5;
    const int lr   = lane >> 2;
    const int lc   = lane & 3;

    const int qt = (T_ / 128 - 1) - blockIdx.x;
    const int h  = blockIdx.y;
    const int b  = blockIdx.z;
    const int q0 = qt * 128;
    const size_t hb = (size_t)(b * NH_ + h);
    const int Tp = T_ / 2;

    // ---- load Q tile (plain loads, once) ----
#pragma unroll
    for (int j = 0; j < 8; j++) {
        const int c = tid + 256 * j;
        const int row = c >> 4, cc = c & 15;
        uint2 vh = *reinterpret_cast<const uint2*>(
            &g_qhi[(hb * T_ + q0 + row) * 32 + cc * 2]);
        uint2 vl = *reinterpret_cast<const uint2*>(
            &g_qlo[(hb * T_ + q0 + row) * 32 + cc * 2]);
        *reinterpret_cast<uint2*>(&Qhi[row * FS + cc * 2]) = vh;
        *reinterpret_cast<uint2*>(&Qlo[row * FS + cc * 2]) = vl;
    }

    auto prefetch_kv = [&](int kt, int s) {
        const uint32_t base = sm_u32 + (9216 + s * F_STAGE) * 4;
#pragma unroll
        for (int j = 0; j < 2; j++) {
            const int idx = tid + 256 * j;
            const int row = idx >> 3, ch = idx & 7;
            const uint32_t soff = (row * FS + ch * 4) * 4;
            cp16(base + soff,
                 &g_khi[(hb * T_ + kt * 64 + row) * 32 + ch * 4]);
            cp16(base + 2304 * 4 + soff,
                 &g_klo[(hb * T_ + kt * 64 + row) * 32 + ch * 4]);
            cp16(base + 4608 * 4 + soff,
                 &g_vthi[(hb * HD_ + row) * Tp + kt * 32 + ch * 4]);
            cp16(base + 6912 * 4 + soff,
                 &g_vtlo[(hb * HD_ + row) * Tp + kt * 32 + ch * 4]);
        }
    };

    float O[8][4];
#pragma unroll
    for (int nt = 0; nt < 8; nt++)
#pragma unroll
        for (int j = 0; j < 4; j++) O[nt][j] = 0.f;
    float m0 = -INFINITY, m1 = -INFINITY, l0 = 0.f, l1 = 0.f;

    const int kt_max = 2 * qt + 1;

    prefetch_kv(0, 0);
    CP_COMMIT();

    for (int kt = 0; kt <= kt_max; kt++) {
        if (kt < kt_max) {
            prefetch_kv(kt + 1, (kt + 1) & 1);
            CP_COMMIT();
            CP_WAIT_1();
        } else {
            CP_WAIT_0();
        }
        __syncthreads();

        const uint32_t* Khi = sm + 9216 + (kt & 1) * F_STAGE;
        const uint32_t* Klo = Khi + 2304;
        const uint32_t* Vhi = Khi + 4608;
        const uint32_t* Vlo = Khi + 6912;

        const int rel = kt * 64 - q0;
        if (rel <= wid * 16 + 15) {
            // ---- S = Q @ K^T ----
            float sf[8][4];
#pragma unroll
            for (int nt = 0; nt < 8; nt++)
#pragma unroll
                for (int j = 0; j < 4; j++) sf[nt][j] = 0.f;

#pragma unroll
            for (int ks = 0; ks < 4; ks++) {
                const int arow = wid * 16 + lr;
                const int koff = ks * 8 + lc;
                uint32_t ahi[4], alo[4];
                ahi[0] = Qhi[arow * FS + koff];
                ahi[1] = Qhi[(arow + 8) * FS + koff];
                ahi[2] = Qhi[arow * FS + koff + 4];
                ahi[3] = Qhi[(arow + 8) * FS + koff + 4];
                alo[0] = Qlo[arow * FS + koff];
                alo[1] = Qlo[(arow + 8) * FS + koff];
                alo[2] = Qlo[arow * FS + koff + 4];
                alo[3] = Qlo[(arow + 8) * FS + koff + 4];
#pragma unroll
                for (int nt = 0; nt < 8; nt++) {
                    const int n = nt * 8 + lr;
                    uint32_t bh[2] = {Khi[n * FS + koff], Khi[n * FS + koff + 4]};
                    uint32_t bl[2] = {Klo[n * FS + koff], Klo[n * FS + koff + 4]};
                    mma_bf16(sf[nt], ahi, bh);
                    mma_bf16(sf[nt], ahi, bl);
                    mma_bf16(sf[nt], alo, bh);
                }
            }

            // ---- causal mask ----
            if (rel + 63 > wid * 16) {
                const int r0 = wid * 16 + lr;
#pragma unroll
                for (int nt = 0; nt < 8; nt++) {
                    const int c0 = rel + nt * 8 + 2 * lc;
                    if (c0 > r0)         sf[nt][0] = -INFINITY;
                    if (c0 + 1 > r0)     sf[nt][1] = -INFINITY;
                    if (c0 > r0 + 8)     sf[nt][2] = -INFINITY;
                    if (c0 + 1 > r0 + 8) sf[nt][3] = -INFINITY;
                }
            }

            // ---- online softmax ----
            float ml0 = -INFINITY, ml1 = -INFINITY;
#pragma unroll
            for (int nt = 0; nt < 8; nt++) {
                ml0 = fmaxf(ml0, fmaxf(sf[nt][0], sf[nt][1]));
                ml1 = fmaxf(ml1, fmaxf(sf[nt][2], sf[nt][3]));
            }
            ml0 = fmaxf(ml0, __shfl_xor_sync(0xffffffffu, ml0, 1));
            ml0 = fmaxf(ml0, __shfl_xor_sync(0xffffffffu, ml0, 2));
            ml1 = fmaxf(ml1, __shfl_xor_sync(0xffffffffu, ml1, 1));
            ml1 = fmaxf(ml1, __shfl_xor_sync(0xffffffffu, ml1, 2));

            const float mn0 = fmaxf(m0, ml0);
            const float mn1 = fmaxf(m1, ml1);
            const float al0 = __expf(m0 - mn0);
            const float al1 = __expf(m1 - mn1);

            float rs0 = 0.f, rs1 = 0.f;
#pragma unroll
            for (int nt = 0; nt < 8; nt++) {
                sf[nt][0] = __expf(sf[nt][0] - mn0);
                sf[nt][1] = __expf(sf[nt][1] - mn0);
                sf[nt][2] = __expf(sf[nt][2] - mn1);
                sf[nt][3] = __expf(sf[nt][3] - mn1);
                rs0 += sf[nt][0] + sf[nt][1];
                rs1 += sf[nt][2] + sf[nt][3];
            }
            rs0 += __shfl_xor_sync(0xffffffffu, rs0, 1);
            rs0 += __shfl_xor_sync(0xffffffffu, rs0, 2);
            rs1 += __shfl_xor_sync(0xffffffffu, rs1, 1);
            rs1 += __shfl_xor_sync(0xffffffffu, rs1, 2);

            l0 = l0 * al0 + rs0;
            l1 = l1 * al1 + rs1;
            m0 = mn0; m1 = mn1;
#pragma unroll
            for (int nt = 0; nt < 8; nt++) {
                O[nt][0] *= al0; O[nt][1] *= al0;
                O[nt][2] *= al1; O[nt][3] *= al1;
            }

            // ---- O += P @ V ----
#pragma unroll
            for (int ks = 0; ks < 4; ks++) {
                uint32_t ahi[4], alo[4];
                ahi[0] = pack_hi2(sf[2 * ks][0],     sf[2 * ks][1]);
                ahi[1] = pack_hi2(sf[2 * ks][2],     sf[2 * ks][3]);
                ahi[2] = pack_hi2(sf[2 * ks + 1][0], sf[2 * ks + 1][1]);
                ahi[3] = pack_hi2(sf[2 * ks + 1][2], sf[2 * ks + 1][3]);
                alo[0] = pack_lo2(sf[2 * ks][0],     sf[2 * ks][1]);
                alo[1] = pack_lo2(sf[2 * ks][2],     sf[2 * ks][3]);
                alo[2] = pack_lo2(sf[2 * ks + 1][0], sf[2 * ks + 1][1]);
                alo[3] = pack_lo2(sf[2 * ks + 1][2], sf[2 * ks + 1][3]);
                const int koff = ks * 8 + lc;
#pragma unroll
                for (int nt = 0; nt < 8; nt++) {
                    const int n = nt * 8 + lr;
                    uint32_t bh[2] = {Vhi[n * FS + koff], Vhi[n * FS + koff + 4]};
                    uint32_t bl[2] = {Vlo[n * FS + koff], Vlo[n * FS + koff + 4]};
                    mma_bf16(O[nt], ahi, bh);
                    mma_bf16(O[nt], ahi, bl);
                    mma_bf16(O[nt], alo, bh);
                }
            }
        }
        __syncthreads();
    }

    // ---- normalize + write directly in split bf16-pair format ----
    const float inv0 = 1.0f / l0;
    const float inv1 = 1.0f / l1;
    const int r0 = q0 + wid * 16 + lr;
#pragma unroll
    for (int nt = 0; nt < 8; nt++) {
        const int pcol = h * 32 + nt * 4 + lc;   // pair index within 512
        float a = O[nt][0] * inv0, bb = O[nt][1] * inv0;
        float ccv = O[nt][2] * inv1, d = O[nt][3] * inv1;
        yhi[(size_t)(b * T_ + r0) * 512 + pcol]       = pack_hi2(a, bb);
        ylo[(size_t)(b * T_ + r0) * 512 + pcol]       = pack_lo2(a, bb);
        yhi[(size_t)(b * T_ + r0 + 8) * 512 + pcol]   = pack_hi2(ccv, d);
        ylo[(size_t)(b * T_ + r0 + 8) * 512 + pcol]   = pack_lo2(ccv, d);
    }
}

// ---------------------------------------------------------------------------
// Launch
// ---------------------------------------------------------------------------
extern "C" void kernel_launch(void* const* d_in, const int* in_sizes, int n_in,
                              void* d_out, int out_size) {
    const float* x      = (const float*)d_in[0];
    const float* sin_t  = (const float*)d_in[1];
    const float* cos_t  = (const float*)d_in[2];
    const float* W_qkv  = (const float*)d_in[3];
    const float* W_proj = (const float*)d_in[4];
    float* out = (float*)d_out;

    float* qkv_ptr = nullptr;
    uint32_t *ahi, *alo, *wthi, *wtlo;
    cudaGetSymbolAddress((void**)&qkv_ptr, g_qkv);
    cudaGetSymbolAddress((void**)&ahi, g_ahi);
    cudaGetSymbolAddress((void**)&alo, g_alo);
    cudaGetSymbolAddress((void**)&wthi, g_wthi);
    cudaGetSymbolAddress((void**)&wtlo, g_wtlo);

    const int M = B_ * T_;           // 4096
    const int Kp = DIM_ / 2;         // 512

    cudaFuncSetAttribute(gemm_pre, cudaFuncAttributeMaxDynamicSharedMemorySize,
                         GEMM_SMEM_BYTES);
    cudaFuncSetAttribute(flash_mma, cudaFuncAttributeMaxDynamicSharedMemorySize,
                         FA_SMEM_BYTES);

    // 1) split x; transpose+split W_qkv; QKV GEMM
    conv_rows<<<(M * Kp) / 256, 256>>>(x, ahi, alo, M * Kp);
    {
        dim3 g(3 * DIM_ / 32, DIM_ / 32);
        conv_tr<<<g, 256>>>(W_qkv, wthi, wtlo, DIM_, 3 * DIM_);
    }
    {
        dim3 g((3 * DIM_) / BN, M / BM);
        gemm_pre<<<g, 256, GEMM_SMEM_BYTES>>>(ahi, alo, wthi, wtlo, qkv_ptr,
                                              M, 3 * DIM_, Kp);
    }

    // 2) RoPE + split q/k; transpose + split v
    {
        int total = B_ * T_ * NH_ * (HD_ / 2);
        rope_conv<<<(total + 255) / 256, 256>>>(sin_t, cos_t);
    }
    {
        dim3 g(T_ / 64, NH_, B_);
        vtrans_conv<<<g, 256>>>();
    }

    // 3) Flash attention (writes split output into g_ahi/g_alo)
    {
        dim3 g(T_ / 128, NH_, B_);
        flash_mma<<<g, 256, FA_SMEM_BYTES>>>(ahi, alo);
    }

    // 4) transpose+split W_proj; output projection
    {
        dim3 g(DIM_ / 32, DIM_ / 32);
        conv_tr<<<g, 256>>>(W_proj, wthi, wtlo, DIM_, DIM_);
    }
    {
        dim3 g(DIM_ / BN, M / BM);
        gemm_pre<<<g, 256, GEMM_SMEM_BYTES>>>(ahi, alo, wthi, wtlo, out,
                                              M, DIM_, Kp);
    }
}

// round 6
// speedup vs baseline: 2.9378x; 1.0486x over previous
#include <cuda_runtime.h>
#include <cuda_bf16.h>
#include <math.h>
#include <stdint.h>

#define B_   2
#define T_   2048
#define DIM_ 1024
#define NH_  16
#define HD_  64

// fp32 scratch
__device__ float g_qkv[(size_t)B_ * T_ * 3 * DIM_];

// packed bf16-pair scratch (hi/lo split)
__device__ uint32_t g_ahi[(size_t)4096 * 512];
__device__ uint32_t g_alo[(size_t)4096 * 512];
__device__ uint32_t g_wthi[(size_t)3072 * 512];
__device__ uint32_t g_wtlo[(size_t)3072 * 512];
__device__ uint32_t g_qhi[(size_t)B_ * NH_ * T_ * 32];
__device__ uint32_t g_qlo[(size_t)B_ * NH_ * T_ * 32];
__device__ uint32_t g_khi[(size_t)B_ * NH_ * T_ * 32];
__device__ uint32_t g_klo[(size_t)B_ * NH_ * T_ * 32];
__device__ uint32_t g_vthi[(size_t)B_ * NH_ * HD_ * (T_ / 2)];
__device__ uint32_t g_vtlo[(size_t)B_ * NH_ * HD_ * (T_ / 2)];

__device__ __forceinline__ void mma_bf16(float c[4], const uint32_t a[4],
                                         const uint32_t b[2]) {
    asm volatile(
        "mma.sync.aligned.m16n8k16.row.col.f32.bf16.bf16.f32 "
        "{%0,%1,%2,%3}, {%4,%5,%6,%7}, {%8,%9}, {%0,%1,%2,%3};\n"
        : "+f"(c[0]), "+f"(c[1]), "+f"(c[2]), "+f"(c[3])
        : "r"(a[0]), "r"(a[1]), "r"(a[2]), "r"(a[3]), "r"(b[0]), "r"(b[1]));
}

__device__ __forceinline__ void ldm_x4(uint32_t r[4], uint32_t addr) {
    asm volatile("ldmatrix.sync.aligned.m8n8.x4.shared.b16 {%0,%1,%2,%3}, [%4];\n"
                 : "=r"(r[0]), "=r"(r[1]), "=r"(r[2]), "=r"(r[3])
                 : "r"(addr));
}

__device__ __forceinline__ uint32_t pack_hi2(float x, float y) {
    __nv_bfloat162 p = {__float2bfloat16_rn(x), __float2bfloat16_rn(y)};
    return *reinterpret_cast<uint32_t*>(&p);
}
__device__ __forceinline__ uint32_t pack_lo2(float x, float y) {
    float xh = __bfloat162float(__float2bfloat16_rn(x));
    float yh = __bfloat162float(__float2bfloat16_rn(y));
    __nv_bfloat162 p = {__float2bfloat16_rn(x - xh), __float2bfloat16_rn(y - yh)};
    return *reinterpret_cast<uint32_t*>(&p);
}

__device__ __forceinline__ void cp16(uint32_t dst_smem, const void* src) {
    asm volatile("cp.async.cg.shared.global [%0], [%1], 16;\n"
                 :: "r"(dst_smem), "l"(src));
}
#define CP_COMMIT() asm volatile("cp.async.commit_group;\n" ::: "memory")
#define CP_WAIT_1() asm volatile("cp.async.wait_group 1;\n" ::: "memory")
#define CP_WAIT_0() asm volatile("cp.async.wait_group 0;\n" ::: "memory")

// ===========================================================================
// conv_rows: fp32 [M][K] -> hi/lo bf16-pair [M][K/2]
// ===========================================================================
__global__ __launch_bounds__(256) void conv_rows(const float* __restrict__ src,
                                                 uint32_t* __restrict__ hi,
                                                 uint32_t* __restrict__ lo,
                                                 int npairs) {
    const int i = blockIdx.x * blockDim.x + threadIdx.x;
    if (i >= npairs) return;
    float2 f = *reinterpret_cast<const float2*>(src + (size_t)i * 2);
    hi[i] = pack_hi2(f.x, f.y);
    lo[i] = pack_lo2(f.x, f.y);
}

// ===========================================================================
// conv_tr: fp32 W[K][N] -> transposed hi/lo pairs [N][K/2]
// ===========================================================================
__global__ __launch_bounds__(256) void conv_tr(const float* __restrict__ src,
                                               uint32_t* __restrict__ hi,
                                               uint32_t* __restrict__ lo,
                                               int K, int N) {
    __shared__ float vs[32][33];
    const int tid = threadIdx.x;
    const int n0 = blockIdx.x * 32;
    const int k0 = blockIdx.y * 32;
    const int Kp = K >> 1;
#pragma unroll
    for (int e = 0; e < 4; e++) {
        const int idx = tid + 256 * e;
        const int kl = idx >> 5, nl = idx & 31;
        vs[kl][nl] = src[(size_t)(k0 + kl) * N + n0 + nl];
    }
    __syncthreads();
#pragma unroll
    for (int e = 0; e < 2; e++) {
        const int idx = tid + 256 * e;
        const int nl = idx >> 4, p = idx & 15;
        float f0 = vs[2 * p][nl], f1 = vs[2 * p + 1][nl];
        const size_t o = (size_t)(n0 + nl) * Kp + (k0 >> 1) + p;
        hi[o] = pack_hi2(f0, f1);
        lo[o] = pack_lo2(f0, f1);
    }
}

// ===========================================================================
// gemm_pre: C = A @ B, pre-split operands, cp.async double-buffered, ldmatrix.
// Stage layout (uint32): Ahi[0..2560) Alo[2560..5120) Bhi[5120..6400) Blo[6400..7680)
// ===========================================================================
#define BM 128
#define BN 64
#define SA_STRIDE 20
#define SB_STRIDE 20
#define G_STAGE 7680
#define GEMM_SMEM_BYTES (2 * G_STAGE * 4)

__global__ __launch_bounds__(256) void gemm_pre(const uint32_t* __restrict__ Ahi,
                                                const uint32_t* __restrict__ Alo,
                                                const uint32_t* __restrict__ Bthi,
                                                const uint32_t* __restrict__ Btlo,
                                                float* __restrict__ C,
                                                int M, int N, int Kp) {
    extern __shared__ uint32_t sm[];
    const uint32_t sm_u32 = (uint32_t)__cvta_generic_to_shared(sm);

    const int tid  = threadIdx.x;
    const int lane = tid & 31;
    const int wid  = tid >> 5;
    const int wm   = wid & 3;
    const int wn   = wid >> 2;
    const int lr   = lane >> 2;
    const int lc   = lane & 3;
    const int lt   = lane >> 3;     // ldmatrix tile index 0..3
    const int lrw  = lane & 7;      // ldmatrix row within tile

    const int m0 = blockIdx.y * BM;
    const int n0 = blockIdx.x * BN;

    float acc[2][4][4];
#pragma unroll
    for (int mt = 0; mt < 2; mt++)
#pragma unroll
        for (int nt = 0; nt < 4; nt++)
#pragma unroll
            for (int j = 0; j < 4; j++) acc[mt][nt][j] = 0.f;

    const int Kt = Kp / 16;

    auto prefetch = [&](int kt, int s) {
        const int k0p = kt * 16;
        const uint32_t base = sm_u32 + s * G_STAGE * 4;
#pragma unroll
        for (int j = 0; j < 2; j++) {
            const int idx = tid + 256 * j;
            const int row = idx >> 2, ch = idx & 3;
            cp16(base + (row * SA_STRIDE + ch * 4) * 4,
                 &Ahi[(size_t)(m0 + row) * Kp + k0p + ch * 4]);
            cp16(base + (2560 + row * SA_STRIDE + ch * 4) * 4,
                 &Alo[(size_t)(m0 + row) * Kp + k0p + ch * 4]);
        }
        {
            const int row = tid >> 2, ch = tid & 3;
            cp16(base + (5120 + row * SB_STRIDE + ch * 4) * 4,
                 &Bthi[(size_t)(n0 + row) * Kp + k0p + ch * 4]);
            cp16(base + (6400 + row * SB_STRIDE + ch * 4) * 4,
                 &Btlo[(size_t)(n0 + row) * Kp + k0p + ch * 4]);
        }
    };

    prefetch(0, 0);
    CP_COMMIT();

    for (int kt = 0; kt < Kt; kt++) {
        if (kt + 1 < Kt) {
            prefetch(kt + 1, (kt + 1) & 1);
            CP_COMMIT();
            CP_WAIT_1();
        } else {
            CP_WAIT_0();
        }
        __syncthreads();

        const uint32_t sbase = sm_u32 + (kt & 1) * G_STAGE * 4;

#pragma unroll
        for (int ks = 0; ks < 2; ks++) {
            // A fragments via ldmatrix.x4
            uint32_t ahi[2][4], alo[2][4];
#pragma unroll
            for (int mt = 0; mt < 2; mt++) {
                const int m = wm * 32 + mt * 16 + (lt & 1) * 8 + lrw;
                const uint32_t off = (uint32_t)(m * SA_STRIDE + ks * 8 + (lt >> 1) * 4) * 4;
                ldm_x4(ahi[mt], sbase + off);
                ldm_x4(alo[mt], sbase + 2560 * 4 + off);
            }
            // B fragments (nt-pairs) + MMAs
#pragma unroll
            for (int ntp = 0; ntp < 2; ntp++) {
                const int n = wn * 32 + ntp * 16 + (lt >> 1) * 8 + lrw;
                const uint32_t off = (uint32_t)(n * SB_STRIDE + ks * 8 + (lt & 1) * 4) * 4;
                uint32_t th[4], tl[4];
                ldm_x4(th, sbase + 5120 * 4 + off);
                ldm_x4(tl, sbase + 6400 * 4 + off);
                uint32_t bh0[2] = {th[0], th[1]}, bh1[2] = {th[2], th[3]};
                uint32_t bl0[2] = {tl[0], tl[1]}, bl1[2] = {tl[2], tl[3]};
#pragma unroll
                for (int mt = 0; mt < 2; mt++) {
                    mma_bf16(acc[mt][2 * ntp],     ahi[mt], bh0);
                    mma_bf16(acc[mt][2 * ntp],     ahi[mt], bl0);
                    mma_bf16(acc[mt][2 * ntp],     alo[mt], bh0);
                    mma_bf16(acc[mt][2 * ntp + 1], ahi[mt], bh1);
                    mma_bf16(acc[mt][2 * ntp + 1], ahi[mt], bl1);
                    mma_bf16(acc[mt][2 * ntp + 1], alo[mt], bh1);
                }
            }
        }
        __syncthreads();
    }

#pragma unroll
    for (int mt = 0; mt < 2; mt++) {
#pragma unroll
        for (int nt = 0; nt < 4; nt++) {
            const int row0 = m0 + wm * 32 + mt * 16 + lr;
            const int col  = n0 + wn * 32 + nt * 8 + lc * 2;
            float2 v0 = make_float2(acc[mt][nt][0], acc[mt][nt][1]);
            float2 v1 = make_float2(acc[mt][nt][2], acc[mt][nt][3]);
            *reinterpret_cast<float2*>(&C[(size_t)row0 * N + col]) = v0;
            *reinterpret_cast<float2*>(&C[(size_t)(row0 + 8) * N + col]) = v1;
        }
    }
}

// ===========================================================================
// rope_conv (unchanged)
// ===========================================================================
__global__ __launch_bounds__(256) void rope_conv(const float* __restrict__ sin_t,
                                                 const float* __restrict__ cos_t) {
    const int idx = blockIdx.x * blockDim.x + threadIdx.x;
    const int total = B_ * T_ * NH_ * (HD_ / 2);
    if (idx >= total) return;
    const int i = idx & 31;
    const int h = (idx >> 5) & (NH_ - 1);
    const int bt = idx >> 9;
    const int t = bt & (T_ - 1);
    const int b = bt >> 11;

    const float s = sin_t[t * HD_ + 2 * i];
    const float c = cos_t[t * HD_ + 2 * i];

    const float* row = g_qkv + (size_t)bt * (3 * DIM_);
    const size_t o = ((size_t)(b * NH_ + h) * T_ + t) * 32 + i;

    float2 q = *reinterpret_cast<const float2*>(row + h * HD_ + 2 * i);
    float q0 = (q.x * c - q.y * s) * 0.125f;
    float q1 = (q.y * c + q.x * s) * 0.125f;
    g_qhi[o] = pack_hi2(q0, q1);
    g_qlo[o] = pack_lo2(q0, q1);

    float2 k = *reinterpret_cast<const float2*>(row + DIM_ + h * HD_ + 2 * i);
    float k0 = k.x * c - k.y * s;
    float k1 = k.y * c + k.x * s;
    g_khi[o] = pack_hi2(k0, k1);
    g_klo[o] = pack_lo2(k0, k1);
}

// ===========================================================================
// vtrans_conv (unchanged)
// ===========================================================================
__global__ __launch_bounds__(256) void vtrans_conv() {
    __shared__ float vs[64][65];
    const int tid = threadIdx.x;
    const int t0 = blockIdx.x * 64;
    const int h  = blockIdx.y;
    const int b  = blockIdx.z;

    const int r = tid >> 2;
    const int q = (tid & 3) * 16;
    const float* src = g_qkv + (size_t)(b * T_ + t0 + r) * (3 * DIM_) + 2 * DIM_ + h * HD_;
#pragma unroll
    for (int v = 0; v < 4; v++) {
        float4 f4 = *reinterpret_cast<const float4*>(src + q + v * 4);
        vs[r][q + v * 4 + 0] = f4.x;
        vs[r][q + v * 4 + 1] = f4.y;
        vs[r][q + v * 4 + 2] = f4.z;
        vs[r][q + v * 4 + 3] = f4.w;
    }
    __syncthreads();

    const int Tp = T_ / 2;
#pragma unroll
    for (int j = 0; j < 8; j++) {
        const int c = tid + 256 * j;
        const int d = c >> 5, p = c & 31;
        float f0 = vs[2 * p][d], f1 = vs[2 * p + 1][d];
        const size_t o = ((size_t)(b * NH_ + h) * HD_ + d) * Tp + (t0 >> 1) + p;
        g_vthi[o] = pack_hi2(f0, f1);
        g_vtlo[o] = pack_lo2(f0, f1);
    }
}

// ===========================================================================
// Flash attention, BQ=128, 8 warps, cp.async double-buffered K/V, ldmatrix.
// smem (uint32): Q hi/lo [0..9216); stages at 9216 + s*9216:
//   Khi[0..2304) Klo[2304..4608) Vhi[4608..6912) Vlo[6912..9216)
// ===========================================================================
#define FS 36
#define F_STAGE 9216
#define FA_SMEM_BYTES ((9216 + 2 * F_STAGE) * 4)   // 110,592

__global__ __launch_bounds__(256, 2) void flash_mma(uint32_t* __restrict__ yhi,
                                                    uint32_t* __restrict__ ylo) {
    extern __shared__ uint32_t sm[];
    const uint32_t sm_u32 = (uint32_t)__cvta_generic_to_shared(sm);
    uint32_t* Qhi = sm;
    uint32_t* Qlo = Qhi + 128 * FS;

    const int tid  = threadIdx.x;
    const int lane = tid & 31;
    const int wid  = tid >> 5;
    const int lr   = lane >> 2;
    const int lc   = lane & 3;
    const int lt   = lane >> 3;
    const int lrw  = lane & 7;

    const int qt = (T_ / 128 - 1) - blockIdx.x;
    const int h  = blockIdx.y;
    const int b  = blockIdx.z;
    const int q0 = qt * 128;
    const size_t hb = (size_t)(b * NH_ + h);
    const int Tp = T_ / 2;

    // ---- load Q tile (plain loads, once) ----
#pragma unroll
    for (int j = 0; j < 8; j++) {
        const int c = tid + 256 * j;
        const int row = c >> 4, cc = c & 15;
        uint2 vh = *reinterpret_cast<const uint2*>(
            &g_qhi[(hb * T_ + q0 + row) * 32 + cc * 2]);
        uint2 vl = *reinterpret_cast<const uint2*>(
            &g_qlo[(hb * T_ + q0 + row) * 32 + cc * 2]);
        *reinterpret_cast<uint2*>(&Qhi[row * FS + cc * 2]) = vh;
        *reinterpret_cast<uint2*>(&Qlo[row * FS + cc * 2]) = vl;
    }

    auto prefetch_kv = [&](int kt, int s) {
        const uint32_t base = sm_u32 + (9216 + s * F_STAGE) * 4;
#pragma unroll
        for (int j = 0; j < 2; j++) {
            const int idx = tid + 256 * j;
            const int row = idx >> 3, ch = idx & 7;
            const uint32_t soff = (row * FS + ch * 4) * 4;
            cp16(base + soff,
                 &g_khi[(hb * T_ + kt * 64 + row) * 32 + ch * 4]);
            cp16(base + 2304 * 4 + soff,
                 &g_klo[(hb * T_ + kt * 64 + row) * 32 + ch * 4]);
            cp16(base + 4608 * 4 + soff,
                 &g_vthi[(hb * HD_ + row) * Tp + kt * 32 + ch * 4]);
            cp16(base + 6912 * 4 + soff,
                 &g_vtlo[(hb * HD_ + row) * Tp + kt * 32 + ch * 4]);
        }
    };

    float O[8][4];
#pragma unroll
    for (int nt = 0; nt < 8; nt++)
#pragma unroll
        for (int j = 0; j < 4; j++) O[nt][j] = 0.f;
    float m0 = -INFINITY, m1 = -INFINITY, l0 = 0.f, l1 = 0.f;

    const int kt_max = 2 * qt + 1;

    prefetch_kv(0, 0);
    CP_COMMIT();

    // ldmatrix lane geometry for Q/K/V fragments
    const int qm = wid * 16 + (lt & 1) * 8 + lrw;          // A-operand row
    const int nrow_base = (lt >> 1) * 8 + lrw;             // B-operand row within ntp

    for (int kt = 0; kt <= kt_max; kt++) {
        if (kt < kt_max) {
            prefetch_kv(kt + 1, (kt + 1) & 1);
            CP_COMMIT();
            CP_WAIT_1();
        } else {
            CP_WAIT_0();
        }
        __syncthreads();

        const uint32_t kbase = sm_u32 + (9216 + (kt & 1) * F_STAGE) * 4;

        const int rel = kt * 64 - q0;
        if (rel <= wid * 16 + 15) {
            // ---- S = Q @ K^T ----
            float sf[8][4];
#pragma unroll
            for (int nt = 0; nt < 8; nt++)
#pragma unroll
                for (int j = 0; j < 4; j++) sf[nt][j] = 0.f;

#pragma unroll
            for (int ks = 0; ks < 4; ks++) {
                const uint32_t qoff = (uint32_t)(qm * FS + ks * 8 + (lt >> 1) * 4) * 4;
                uint32_t ahi[4], alo[4];
                ldm_x4(ahi, sm_u32 + qoff);
                ldm_x4(alo, sm_u32 + 4608 * 4 + qoff);
#pragma unroll
                for (int ntp = 0; ntp < 4; ntp++) {
                    const int n = ntp * 16 + nrow_base;
                    const uint32_t koff = (uint32_t)(n * FS + ks * 8 + (lt & 1) * 4) * 4;
                    uint32_t th[4], tl[4];
                    ldm_x4(th, kbase + koff);
                    ldm_x4(tl, kbase + 2304 * 4 + koff);
                    uint32_t bh0[2] = {th[0], th[1]}, bh1[2] = {th[2], th[3]};
                    uint32_t bl0[2] = {tl[0], tl[1]}, bl1[2] = {tl[2], tl[3]};
                    mma_bf16(sf[2 * ntp],     ahi, bh0);
                    mma_bf16(sf[2 * ntp],     ahi, bl0);
                    mma_bf16(sf[2 * ntp],     alo, bh0);
                    mma_bf16(sf[2 * ntp + 1], ahi, bh1);
                    mma_bf16(sf[2 * ntp + 1], ahi, bl1);
                    mma_bf16(sf[2 * ntp + 1], alo, bh1);
                }
            }

            // ---- causal mask ----
            if (rel + 63 > wid * 16) {
                const int r0 = wid * 16 + lr;
#pragma unroll
                for (int nt = 0; nt < 8; nt++) {
                    const int c0 = rel + nt * 8 + 2 * lc;
                    if (c0 > r0)         sf[nt][0] = -INFINITY;
                    if (c0 + 1 > r0)     sf[nt][1] = -INFINITY;
                    if (c0 > r0 + 8)     sf[nt][2] = -INFINITY;
                    if (c0 + 1 > r0 + 8) sf[nt][3] = -INFINITY;
                }
            }

            // ---- online softmax ----
            float ml0 = -INFINITY, ml1 = -INFINITY;
#pragma unroll
            for (int nt = 0; nt < 8; nt++) {
                ml0 = fmaxf(ml0, fmaxf(sf[nt][0], sf[nt][1]));
                ml1 = fmaxf(ml1, fmaxf(sf[nt][2], sf[nt][3]));
            }
            ml0 = fmaxf(ml0, __shfl_xor_sync(0xffffffffu, ml0, 1));
            ml0 = fmaxf(ml0, __shfl_xor_sync(0xffffffffu, ml0, 2));
            ml1 = fmaxf(ml1, __shfl_xor_sync(0xffffffffu, ml1, 1));
            ml1 = fmaxf(ml1, __shfl_xor_sync(0xffffffffu, ml1, 2));

            const float mn0 = fmaxf(m0, ml0);
            const float mn1 = fmaxf(m1, ml1);
            const float al0 = __expf(m0 - mn0);
            const float al1 = __expf(m1 - mn1);

            float rs0 = 0.f, rs1 = 0.f;
#pragma unroll
            for (int nt = 0; nt < 8; nt++) {
                sf[nt][0] = __expf(sf[nt][0] - mn0);
                sf[nt][1] = __expf(sf[nt][1] - mn0);
                sf[nt][2] = __expf(sf[nt][2] - mn1);
                sf[nt][3] = __expf(sf[nt][3] - mn1);
                rs0 += sf[nt][0] + sf[nt][1];
                rs1 += sf[nt][2] + sf[nt][3];
            }
            rs0 += __shfl_xor_sync(0xffffffffu, rs0, 1);
            rs0 += __shfl_xor_sync(0xffffffffu, rs0, 2);
            rs1 += __shfl_xor_sync(0xffffffffu, rs1, 1);
            rs1 += __shfl_xor_sync(0xffffffffu, rs1, 2);

            l0 = l0 * al0 + rs0;
            l1 = l1 * al1 + rs1;
            m0 = mn0; m1 = mn1;
#pragma unroll
            for (int nt = 0; nt < 8; nt++) {
                O[nt][0] *= al0; O[nt][1] *= al0;
                O[nt][2] *= al1; O[nt][3] *= al1;
            }

            // ---- O += P @ V ----
#pragma unroll
            for (int ks = 0; ks < 4; ks++) {
                uint32_t ahi[4], alo[4];
                ahi[0] = pack_hi2(sf[2 * ks][0],     sf[2 * ks][1]);
                ahi[1] = pack_hi2(sf[2 * ks][2],     sf[2 * ks][3]);
                ahi[2] = pack_hi2(sf[2 * ks + 1][0], sf[2 * ks + 1][1]);
                ahi[3] = pack_hi2(sf[2 * ks + 1][2], sf[2 * ks + 1][3]);
                alo[0] = pack_lo2(sf[2 * ks][0],     sf[2 * ks][1]);
                alo[1] = pack_lo2(sf[2 * ks][2],     sf[2 * ks][3]);
                alo[2] = pack_lo2(sf[2 * ks + 1][0], sf[2 * ks + 1][1]);
                alo[3] = pack_lo2(sf[2 * ks + 1][2], sf[2 * ks + 1][3]);
#pragma unroll
                for (int ntp = 0; ntp < 4; ntp++) {
                    const int n = ntp * 16 + nrow_base;
                    const uint32_t voff = (uint32_t)(n * FS + ks * 8 + (lt & 1) * 4) * 4;
                    uint32_t th[4], tl[4];
                    ldm_x4(th, kbase + 4608 * 4 + voff);
                    ldm_x4(tl, kbase + 6912 * 4 + voff);
                    uint32_t bh0[2] = {th[0], th[1]}, bh1[2] = {th[2], th[3]};
                    uint32_t bl0[2] = {tl[0], tl[1]}, bl1[2] = {tl[2], tl[3]};
                    mma_bf16(O[2 * ntp],     ahi, bh0);
                    mma_bf16(O[2 * ntp],     ahi, bl0);
                    mma_bf16(O[2 * ntp],     alo, bh0);
                    mma_bf16(O[2 * ntp + 1], ahi, bh1);
                    mma_bf16(O[2 * ntp + 1], ahi, bl1);
                    mma_bf16(O[2 * ntp + 1], alo, bh1);
                }
            }
        }
        __syncthreads();
    }

    // ---- normalize + write split bf16-pair output ----
    const float inv0 = 1.0f / l0;
    const float inv1 = 1.0f / l1;
    const int r0 = q0 + wid * 16 + lr;
#pragma unroll
    for (int nt = 0; nt < 8; nt++) {
        const int pcol = h * 32 + nt * 4 + lc;
        float a = O[nt][0] * inv0, bb = O[nt][1] * inv0;
        float ccv = O[nt][2] * inv1, d = O[nt][3] * inv1;
        yhi[(size_t)(b * T_ + r0) * 512 + pcol]     = pack_hi2(a, bb);
        ylo[(size_t)(b * T_ + r0) * 512 + pcol]     = pack_lo2(a, bb);
        yhi[(size_t)(b * T_ + r0 + 8) * 512 + pcol] = pack_hi2(ccv, d);
        ylo[(size_t)(b * T_ + r0 + 8) * 512 + pcol] = pack_lo2(ccv, d);
    }
}

// ---------------------------------------------------------------------------
// Launch
// ---------------------------------------------------------------------------
extern "C" void kernel_launch(void* const* d_in, const int* in_sizes, int n_in,
                              void* d_out, int out_size) {
    const float* x      = (const float*)d_in[0];
    const float* sin_t  = (const float*)d_in[1];
    const float* cos_t  = (const float*)d_in[2];
    const float* W_qkv  = (const float*)d_in[3];
    const float* W_proj = (const float*)d_in[4];
    float* out = (float*)d_out;

    float* qkv_ptr = nullptr;
    uint32_t *ahi, *alo, *wthi, *wtlo;
    cudaGetSymbolAddress((void**)&qkv_ptr, g_qkv);
    cudaGetSymbolAddress((void**)&ahi, g_ahi);
    cudaGetSymbolAddress((void**)&alo, g_alo);
    cudaGetSymbolAddress((void**)&wthi, g_wthi);
    cudaGetSymbolAddress((void**)&wtlo, g_wtlo);

    const int M = B_ * T_;
    const int Kp = DIM_ / 2;

    cudaFuncSetAttribute(gemm_pre, cudaFuncAttributeMaxDynamicSharedMemorySize,
                         GEMM_SMEM_BYTES);
    cudaFuncSetAttribute(flash_mma, cudaFuncAttributeMaxDynamicSharedMemorySize,
                         FA_SMEM_BYTES);

    // 1) split x; transpose+split W_qkv; QKV GEMM
    conv_rows<<<(M * Kp) / 256, 256>>>(x, ahi, alo, M * Kp);
    {
        dim3 g(3 * DIM_ / 32, DIM_ / 32);
        conv_tr<<<g, 256>>>(W_qkv, wthi, wtlo, DIM_, 3 * DIM_);
    }
    {
        dim3 g((3 * DIM_) / BN, M / BM);
        gemm_pre<<<g, 256, GEMM_SMEM_BYTES>>>(ahi, alo, wthi, wtlo, qkv_ptr,
                                              M, 3 * DIM_, Kp);
    }

    // 2) RoPE + split q/k; transpose + split v
    {
        int total = B_ * T_ * NH_ * (HD_ / 2);
        rope_conv<<<(total + 255) / 256, 256>>>(sin_t, cos_t);
    }
    {
        dim3 g(T_ / 64, NH_, B_);
        vtrans_conv<<<g, 256>>>();
    }

    // 3) Flash attention
    {
        dim3 g(T_ / 128, NH_, B_);
        flash_mma<<<g, 256, FA_SMEM_BYTES>>>(ahi, alo);
    }

    // 4) transpose+split W_proj; output projection
    {
        dim3 g(DIM_ / 32, DIM_ / 32);
        conv_tr<<<g, 256>>>(W_proj, wthi, wtlo, DIM_, DIM_);
    }
    {
        dim3 g(DIM_ / BN, M / BM);
        gemm_pre<<<g, 256, GEMM_SMEM_BYTES>>>(ahi, alo, wthi, wtlo, out,
                                              M, DIM_, Kp);
    }
}